// round 7
// baseline (speedup 1.0000x reference)
#include <cuda_runtime.h>
#include <cuda_bf16.h>
#include <stdint.h>

#define N_B   8
#define SEQ   2048
#define EMB   512
#define H     8
#define HD    64
#define NROWS (N_B*SEQ)
#define NH    (N_B*H)

// fragment-pair permutation within groups of 8 kp
#define RP(j)  (((((j)&3))<<1) | (((j)>>2)&1))
__device__ __forceinline__ int reord(int kp) { return (kp & ~7) | RP(kp & 7); }

// -------- scratch (no cudaMalloc allowed) --------
__device__ uint32_t g_wh[4*EMB*256], g_wl[4*EMB*256];        // [slot][n][kp']
__device__ uint32_t g_xh[(size_t)3*NROWS*256], g_xl[(size_t)3*NROWS*256]; // [inp][row][kp']
__device__ uint32_t g_qh[(size_t)NH*SEQ*32], g_ql[(size_t)NH*SEQ*32];     // [nh][s][dp']
__device__ uint32_t g_kh[(size_t)NH*SEQ*32], g_kl[(size_t)NH*SEQ*32];
__device__ uint32_t g_vh[(size_t)NH*HD*(SEQ/2)], g_vl[(size_t)NH*HD*(SEQ/2)]; // [nh][d][sp']
__device__ uint32_t g_aoh[(size_t)NROWS*256], g_aol[(size_t)NROWS*256];   // [row][kp']

// ---------------- helpers ----------------
__device__ __forceinline__ uint32_t pack2(__nv_bfloat16 a, __nv_bfloat16 b) {
    return ((uint32_t)__bfloat16_as_ushort(b) << 16) | (uint32_t)__bfloat16_as_ushort(a);
}
__device__ __forceinline__ void splitb(float x, __nv_bfloat16 &h, __nv_bfloat16 &l) {
    h = __float2bfloat16_rn(x);
    l = __float2bfloat16_rn(x - __bfloat162float(h));
}
__device__ __forceinline__ void split_pack(float x0, float x1, uint32_t &hi, uint32_t &lo) {
    __nv_bfloat16 h0, l0, h1, l1;
    splitb(x0, h0, l0); splitb(x1, h1, l1);
    hi = pack2(h0, h1); lo = pack2(l0, l1);
}
__device__ __forceinline__ void mmab(float c[4], const uint32_t a[4], uint32_t b0, uint32_t b1) {
    asm volatile(
      "mma.sync.aligned.m16n8k16.row.col.f32.bf16.bf16.f32 "
      "{%0,%1,%2,%3},{%4,%5,%6,%7},{%8,%9},{%0,%1,%2,%3};\n"
      : "+f"(c[0]), "+f"(c[1]), "+f"(c[2]), "+f"(c[3])
      : "r"(a[0]), "r"(a[1]), "r"(a[2]), "r"(a[3]), "r"(b0), "r"(b1));
}
__device__ __forceinline__ void cpa16(void* s, const void* g) {
    uint32_t sa = (uint32_t)__cvta_generic_to_shared(s);
    asm volatile("cp.async.cg.shared.global [%0], [%1], 16;" :: "r"(sa), "l"(g) : "memory");
}
#define CPCOMMIT() asm volatile("cp.async.commit_group;" ::: "memory")
#define CPWAIT(n)  asm volatile("cp.async.wait_group %0;" :: "n"(n) : "memory")

// ============================================================
// split_w: W[k][n] f32 -> [slot][n][kp'] packed bf16 hi/lo
// ============================================================
__global__ __launch_bounds__(256) void split_w(
    const float* __restrict__ Wv, const float* __restrict__ Wk,
    const float* __restrict__ Wq, const float* __restrict__ Wo)
{
    const int slot = blockIdx.y;
    const float* src = (slot==0)?Wv:(slot==1)?Wk:(slot==2)?Wq:Wo;
    int i = blockIdx.x * 256 + threadIdx.x;   // 0..131071
    int n = i >> 8, kp = i & 255;
    float x0 = src[(2*kp  ) * EMB + n];
    float x1 = src[(2*kp+1) * EMB + n];
    uint32_t hi, lo; split_pack(x0, x1, hi, lo);
    size_t o = (size_t)slot*EMB*256 + (size_t)n*256 + reord(kp);
    g_wh[o] = hi; g_wl[o] = lo;
}

// ============================================================
// split_x: inputs [row][k] f32 -> [inp][row][kp'] packed hi/lo
// ============================================================
__global__ __launch_bounds__(256) void split_x(
    const float* __restrict__ values, const float* __restrict__ keys,
    const float* __restrict__ query)
{
    const int inp = blockIdx.y;   // 0:v 1:k 2:q
    const float* src = (inp==0)?values:(inp==1)?keys:query;
    int i = blockIdx.x * 256 + threadIdx.x;
    int row = i >> 8, kp = i & 255;
    float2 v = *(const float2*)(src + (size_t)row*EMB + 2*kp);
    uint32_t hi, lo; split_pack(v.x, v.y, hi, lo);
    size_t o = (size_t)inp*NROWS*256 + (size_t)row*256 + reord(kp);
    g_xh[o] = hi; g_xl[o] = lo;
}

// ============================================================
// bf16x3 GEMM core, all operands pre-split/pre-permuted.
// smem tiles 128x16 u32, stride 24 (conflict-free LDS.64).
// ============================================================
#define GST 24
#define GTILE (128*GST)             // u32 per buf
#define GEMM_SMEM (8*GTILE*4)       // Ah,Al,Bh,Bl x 2 bufs = 98304 B

__device__ __forceinline__ void gemm_prefetch(
    const uint32_t* __restrict__ Xh, const uint32_t* __restrict__ Xl,
    const uint32_t* __restrict__ Wh, const uint32_t* __restrict__ Wl,
    uint32_t* Ah, uint32_t* Al, uint32_t* Bh, uint32_t* Bl,
    int m0, int n0, int kp0, int buf, int tid)
{
    #pragma unroll
    for (int it = 0; it < 2; it++) {
        int f = tid + 256 * it;
        int row = f >> 2, c4 = f & 3;
        size_t ga = (size_t)(m0 + row) * 256 + kp0 + c4 * 4;
        size_t gb = (size_t)(n0 + row) * 256 + kp0 + c4 * 4;
        int so = (buf*128 + row) * GST + c4 * 4;
        cpa16(&Ah[so], Xh + ga);
        cpa16(&Al[so], Xl + ga);
        cpa16(&Bh[so], Wh + gb);
        cpa16(&Bl[so], Wl + gb);
    }
}

__device__ __forceinline__ void gemm_core(
    const uint32_t* __restrict__ Xh, const uint32_t* __restrict__ Xl,
    const uint32_t* __restrict__ Wh, const uint32_t* __restrict__ Wl,
    uint32_t* smu, float c[2][8][4], int m0, int n0, int tid)
{
    uint32_t* Ah = smu;
    uint32_t* Al = Ah + 2*GTILE;
    uint32_t* Bh = Al + 2*GTILE;
    uint32_t* Bl = Bh + 2*GTILE;

    const int lane = tid & 31, w = tid >> 5;
    const int g = lane >> 2, cq = lane & 3;
    const int wm = (w & 3) * 32, wn = (w >> 2) * 64;

    #pragma unroll
    for (int mt = 0; mt < 2; mt++)
        #pragma unroll
        for (int nt = 0; nt < 8; nt++)
            #pragma unroll
            for (int e = 0; e < 4; e++) c[mt][nt][e] = 0.f;

    gemm_prefetch(Xh, Xl, Wh, Wl, Ah, Al, Bh, Bl, m0, n0, 0, 0, tid);
    CPCOMMIT();

    for (int t = 0; t < 16; t++) {
        if (t < 15) {
            gemm_prefetch(Xh, Xl, Wh, Wl, Ah, Al, Bh, Bl, m0, n0, (t+1)*16, (t+1)&1, tid);
            CPCOMMIT();
            CPWAIT(1);
        } else {
            CPWAIT(0);
        }
        __syncthreads();

        const int bb = (t & 1) * 128;
        #pragma unroll
        for (int ks = 0; ks < 2; ks++) {
            const int kc = ks*8 + 2*cq;
            uint32_t ah[2][4], al[2][4];
            #pragma unroll
            for (int mt = 0; mt < 2; mt++) {
                int r0 = (bb + wm + mt*16 + g) * GST + kc;
                uint2 h0 = *(uint2*)&Ah[r0];
                uint2 h1 = *(uint2*)&Ah[r0 + 8*GST];
                uint2 l0 = *(uint2*)&Al[r0];
                uint2 l1 = *(uint2*)&Al[r0 + 8*GST];
                ah[mt][0]=h0.x; ah[mt][1]=h1.x; ah[mt][2]=h0.y; ah[mt][3]=h1.y;
                al[mt][0]=l0.x; al[mt][1]=l1.x; al[mt][2]=l0.y; al[mt][3]=l1.y;
            }
            #pragma unroll
            for (int nt = 0; nt < 8; nt++) {
                int ro = (bb + wn + nt*8 + g) * GST + kc;
                uint2 bh2 = *(uint2*)&Bh[ro];
                uint2 bl2 = *(uint2*)&Bl[ro];
                #pragma unroll
                for (int mt = 0; mt < 2; mt++) {
                    mmab(c[mt][nt], ah[mt], bh2.x, bh2.y);
                    mmab(c[mt][nt], al[mt], bh2.x, bh2.y);
                    mmab(c[mt][nt], ah[mt], bl2.x, bl2.y);
                }
            }
        }
        __syncthreads();
    }
}

// ============================================================
// Projections
// ============================================================
__global__ __launch_bounds__(256, 2) void proj_kernel()
{
    extern __shared__ uint32_t smu[];
    const int which = blockIdx.z;   // 0:v 1:k 2:q
    const uint32_t* Xh = g_xh + (size_t)which*NROWS*256;
    const uint32_t* Xl = g_xl + (size_t)which*NROWS*256;
    const uint32_t* Wh = g_wh + (size_t)which*EMB*256;
    const uint32_t* Wl = g_wl + (size_t)which*EMB*256;

    const int m0 = blockIdx.y * 128, n0 = blockIdx.x * 128;
    float c[2][8][4];
    gemm_core(Xh, Xl, Wh, Wl, smu, c, m0, n0, threadIdx.x);

    const int lane = threadIdx.x & 31, w = threadIdx.x >> 5;
    const int g = lane >> 2, cq = lane & 3;
    const int wm = (w & 3) * 32, wn = (w >> 2) * 64;
    const int nb = m0 >> 11;     // batch (tile doesn't straddle batches)

    if (which != 0) {
        // Q or K: [nh][s][dp'] packed along d
        uint32_t* dh = (which == 2) ? g_qh : g_kh;
        uint32_t* dl = (which == 2) ? g_ql : g_kl;
        const float post = (which == 2) ? 0.125f : 1.0f;
        #pragma unroll
        for (int mt = 0; mt < 2; mt++)
            #pragma unroll
            for (int half = 0; half < 2; half++) {
                int row = m0 + wm + mt*16 + g + half*8;
                int s = row & 2047;
                #pragma unroll
                for (int nt = 0; nt < 8; nt++) {
                    int col = n0 + wn + nt*8 + 2*cq;
                    int h = col >> 6;
                    int dp = reord(nt*4 + cq);
                    size_t base = ((size_t)(nb*H + h)*SEQ + s)*32 + dp;
                    uint32_t hi, lo;
                    split_pack(c[mt][nt][half*2+0]*post, c[mt][nt][half*2+1]*post, hi, lo);
                    dh[base] = hi; dl[base] = lo;
                }
            }
    } else {
        // V: stage fp32 tile, then transpose-pack to [nh][d][sp']
        float* st = (float*)smu;   // 128 x stride 130 fp32
        #pragma unroll
        for (int mt = 0; mt < 2; mt++)
            #pragma unroll
            for (int half = 0; half < 2; half++) {
                int sl = wm + mt*16 + g + half*8;
                #pragma unroll
                for (int nt = 0; nt < 8; nt++) {
                    int lc = wn + nt*8 + 2*cq;
                    *(float2*)&st[sl*130 + lc] =
                        make_float2(c[mt][nt][half*2+0], c[mt][nt][half*2+1]);
                }
            }
        __syncthreads();
        const int sbase = (m0 & 2047) >> 1;   // multiple of 64
        #pragma unroll
        for (int it = 0; it < 32; it++) {
            int idx = threadIdx.x + 256 * it;  // 8192 items
            int spl = idx & 63, lc = idx >> 6;
            float v0 = st[(2*spl  )*130 + lc];
            float v1 = st[(2*spl+1)*130 + lc];
            uint32_t hi, lo; split_pack(v0, v1, hi, lo);
            int h = (n0 + lc) >> 6, d = lc & 63;
            size_t o = ((size_t)(nb*H + h)*HD + d)*(SEQ/2) + sbase + reord(spl);
            g_vh[o] = hi; g_vl[o] = lo;
        }
    }
}

// ============================================================
// Output GEMM: out = ao @ Wo + bo
// ============================================================
__global__ __launch_bounds__(256, 2) void out_kernel(
    const float* __restrict__ bo, float* __restrict__ out)
{
    extern __shared__ uint32_t smu[];
    const int m0 = blockIdx.y * 128, n0 = blockIdx.x * 128;
    float c[2][8][4];
    gemm_core(g_aoh, g_aol, g_wh + (size_t)3*EMB*256, g_wl + (size_t)3*EMB*256,
              smu, c, m0, n0, threadIdx.x);

    const int lane = threadIdx.x & 31, w = threadIdx.x >> 5;
    const int g = lane >> 2, cq = lane & 3;
    const int wm = (w & 3) * 32, wn = (w >> 2) * 64;

    #pragma unroll
    for (int mt = 0; mt < 2; mt++)
        #pragma unroll
        for (int half = 0; half < 2; half++) {
            size_t row = m0 + wm + mt*16 + g + half*8;
            #pragma unroll
            for (int nt = 0; nt < 8; nt++) {
                int col = n0 + wn + nt*8 + 2*cq;
                float2 v = make_float2(c[mt][nt][half*2+0] + bo[col],
                                       c[mt][nt][half*2+1] + bo[col+1]);
                *(float2*)&out[row * EMB + col] = v;
            }
        }
}

// ============================================================
// Flash attention: BQ=128, BKV=32, all operands vectorized.
// ============================================================
#define BQF 128
#define BKV 32
#define KSTR 40    // K smem stride (32 kp' cols)
#define VSTR 24    // V smem stride (16 sp' cols)
#define FK (2*BKV*KSTR)        // 2560 u32 per K array
#define FV (2*HD*VSTR)         // 3072 u32 per V array
#define FL_MS (2*FK + 2*FV)
#define FLASH_SMEM ((FL_MS + 2*BKV) * 4)

__global__ __launch_bounds__(256, 2) void flash_kernel(const int* __restrict__ mask)
{
    extern __shared__ uint32_t smu[];
    uint32_t* Kh = smu;
    uint32_t* Kl = Kh + FK;
    uint32_t* Vh = Kl + FK;
    uint32_t* Vl = Vh + FV;
    int*      ms = (int*)(Vl + FV);

    const int tid = threadIdx.x;
    const int lane = tid & 31, w = tid >> 5;
    const int g = lane >> 2, cq = lane & 3;
    const int q0 = blockIdx.x * BQF;
    const int nh = blockIdx.y;
    const int n = nh >> 3, h = nh & 7;
    const uint32_t* Qhg = g_qh + (size_t)nh * SEQ * 32;
    const uint32_t* Qlg = g_ql + (size_t)nh * SEQ * 32;
    const uint32_t* Khg = g_kh + (size_t)nh * SEQ * 32;
    const uint32_t* Klg = g_kl + (size_t)nh * SEQ * 32;
    const uint32_t* Vhg = g_vh + (size_t)nh * HD * (SEQ/2);
    const uint32_t* Vlg = g_vl + (size_t)nh * HD * (SEQ/2);
    const int* mrow = mask + n * SEQ;
    const int rb = w * 16 + g;

    // ---- prefetch k-tile 0 ----
    {
        int kr = tid >> 3, kc = tid & 7;          // K: 32 rows x 32 u32
        cpa16(&Kh[kr*KSTR + kc*4], Khg + (size_t)kr*32 + kc*4);
        cpa16(&Kl[kr*KSTR + kc*4], Klg + (size_t)kr*32 + kc*4);
        int vr = tid >> 2, vc = tid & 3;          // V: 64 rows x 16 u32
        cpa16(&Vh[vr*VSTR + vc*4], Vhg + (size_t)vr*(SEQ/2) + vc*4);
        cpa16(&Vl[vr*VSTR + vc*4], Vlg + (size_t)vr*(SEQ/2) + vc*4);
        if (tid < 8) cpa16(&ms[tid*4], mrow + tid*4);
        CPCOMMIT();
    }

    // ---- Q fragments: vector LDG, pre-split/permuted/scaled ----
    uint32_t qh[4][4], ql[4][4];
    {
        const size_t r0 = (size_t)(q0 + rb) * 32, r1 = r0 + 8*32;
        #pragma unroll
        for (int ks = 0; ks < 4; ks++) {
            int o = ks*8 + 2*cq;
            uint2 h0 = *(const uint2*)(Qhg + r0 + o);
            uint2 h1 = *(const uint2*)(Qhg + r1 + o);
            uint2 l0 = *(const uint2*)(Qlg + r0 + o);
            uint2 l1 = *(const uint2*)(Qlg + r1 + o);
            qh[ks][0]=h0.x; qh[ks][1]=h1.x; qh[ks][2]=h0.y; qh[ks][3]=h1.y;
            ql[ks][0]=l0.x; ql[ks][1]=l1.x; ql[ks][2]=l0.y; ql[ks][3]=l1.y;
        }
    }

    float acc[8][4];
    float mi[2] = {-1e30f, -1e30f}, li[2] = {0.f, 0.f};
    #pragma unroll
    for (int nt = 0; nt < 8; nt++)
        #pragma unroll
        for (int e = 0; e < 4; e++) acc[nt][e] = 0.f;

    for (int t = 0; t < SEQ / BKV; t++) {
        const int cur = t & 1, nxt = cur ^ 1;
        if (t < SEQ / BKV - 1) {
            const int k0 = (t + 1) * BKV;
            int kr = tid >> 3, kc = tid & 7;
            cpa16(&Kh[(nxt*BKV+kr)*KSTR + kc*4], Khg + (size_t)(k0+kr)*32 + kc*4);
            cpa16(&Kl[(nxt*BKV+kr)*KSTR + kc*4], Klg + (size_t)(k0+kr)*32 + kc*4);
            int vr = tid >> 2, vc = tid & 3;
            cpa16(&Vh[(nxt*HD+vr)*VSTR + vc*4], Vhg + (size_t)vr*(SEQ/2) + k0/2 + vc*4);
            cpa16(&Vl[(nxt*HD+vr)*VSTR + vc*4], Vlg + (size_t)vr*(SEQ/2) + k0/2 + vc*4);
            if (tid < 8) cpa16(&ms[nxt*BKV + tid*4], mrow + k0 + tid*4);
            CPCOMMIT();
            CPWAIT(1);
        } else {
            CPWAIT(0);
        }
        __syncthreads();

        const uint32_t* KhC = Kh + cur * BKV * KSTR;
        const uint32_t* KlC = Kl + cur * BKV * KSTR;
        const uint32_t* VhC = Vh + cur * HD * VSTR;
        const uint32_t* VlC = Vl + cur * HD * VSTR;
        const int*      msC = ms + cur * BKV;

        // ---- S = Q @ K^T ----
        float s[4][4];
        #pragma unroll
        for (int nt = 0; nt < 4; nt++)
            #pragma unroll
            for (int e = 0; e < 4; e++) s[nt][e] = 0.f;

        #pragma unroll
        for (int ks = 0; ks < 4; ks++) {
            const int kc = ks*8 + 2*cq;
            #pragma unroll
            for (int nt = 0; nt < 4; nt++) {
                int ro = (nt*8 + g)*KSTR + kc;
                uint2 bh2 = *(uint2*)&KhC[ro];
                uint2 bl2 = *(uint2*)&KlC[ro];
                mmab(s[nt], qh[ks], bh2.x, bh2.y);
                mmab(s[nt], ql[ks], bh2.x, bh2.y);
                mmab(s[nt], qh[ks], bl2.x, bl2.y);
            }
        }

        // ---- mask + online softmax ----
        float mx0 = -1e30f, mx1 = -1e30f;
        #pragma unroll
        for (int nt = 0; nt < 4; nt++) {
            #pragma unroll
            for (int j = 0; j < 2; j++) {
                int mv = msC[nt*8 + 2*cq + j];
                float v0 = mv ? s[nt][j]   : -1e30f;
                float v1 = mv ? s[nt][2+j] : -1e30f;
                s[nt][j] = v0; s[nt][2+j] = v1;
                mx0 = fmaxf(mx0, v0); mx1 = fmaxf(mx1, v1);
            }
        }
        mx0 = fmaxf(mx0, __shfl_xor_sync(0xffffffffu, mx0, 1));
        mx0 = fmaxf(mx0, __shfl_xor_sync(0xffffffffu, mx0, 2));
        mx1 = fmaxf(mx1, __shfl_xor_sync(0xffffffffu, mx1, 1));
        mx1 = fmaxf(mx1, __shfl_xor_sync(0xffffffffu, mx1, 2));

        float mn0 = fmaxf(mi[0], mx0), mn1 = fmaxf(mi[1], mx1);
        float cr0 = __expf(mi[0] - mn0), cr1 = __expf(mi[1] - mn1);
        float sum0 = 0.f, sum1 = 0.f;
        #pragma unroll
        for (int nt = 0; nt < 4; nt++) {
            s[nt][0] = __expf(s[nt][0] - mn0);
            s[nt][1] = __expf(s[nt][1] - mn0);
            s[nt][2] = __expf(s[nt][2] - mn1);
            s[nt][3] = __expf(s[nt][3] - mn1);
            sum0 += s[nt][0] + s[nt][1];
            sum1 += s[nt][2] + s[nt][3];
        }
        sum0 += __shfl_xor_sync(0xffffffffu, sum0, 1);
        sum0 += __shfl_xor_sync(0xffffffffu, sum0, 2);
        sum1 += __shfl_xor_sync(0xffffffffu, sum1, 1);
        sum1 += __shfl_xor_sync(0xffffffffu, sum1, 2);
        li[0] = li[0] * cr0 + sum0; mi[0] = mn0;
        li[1] = li[1] * cr1 + sum1; mi[1] = mn1;
        #pragma unroll
        for (int nt = 0; nt < 8; nt++) {
            acc[nt][0] *= cr0; acc[nt][1] *= cr0;
            acc[nt][2] *= cr1; acc[nt][3] *= cr1;
        }

        // ---- P fragments: register repack ----
        uint32_t ph[2][4], pl[2][4];
        #pragma unroll
        for (int k2 = 0; k2 < 2; k2++) {
            split_pack(s[2*k2  ][0], s[2*k2  ][1], ph[k2][0], pl[k2][0]);
            split_pack(s[2*k2  ][2], s[2*k2  ][3], ph[k2][1], pl[k2][1]);
            split_pack(s[2*k2+1][0], s[2*k2+1][1], ph[k2][2], pl[k2][2]);
            split_pack(s[2*k2+1][2], s[2*k2+1][3], ph[k2][3], pl[k2][3]);
        }

        // ---- O += P @ V ----
        #pragma unroll
        for (int k2 = 0; k2 < 2; k2++) {
            const int kc = k2*8 + 2*cq;
            #pragma unroll
            for (int nt = 0; nt < 8; nt++) {
                int ro = (nt*8 + g)*VSTR + kc;
                uint2 vh2 = *(uint2*)&VhC[ro];
                uint2 vl2 = *(uint2*)&VlC[ro];
                mmab(acc[nt], ph[k2], vh2.x, vh2.y);
                mmab(acc[nt], pl[k2], vh2.x, vh2.y);
                mmab(acc[nt], ph[k2], vl2.x, vl2.y);
            }
        }
        __syncthreads();
    }

    // ---- epilogue: write pre-split packed ao ----
    float inv0 = 1.f / li[0], inv1 = 1.f / li[1];
    #pragma unroll
    for (int nt = 0; nt < 8; nt++) {
        int kpp = reord((h*32 + nt*4 + cq) & 7) | ((h*32 + nt*4 + cq) & ~7);
        size_t r0 = (size_t)(n*SEQ + q0 + rb) * 256 + kpp;
        size_t r1 = (size_t)(n*SEQ + q0 + rb + 8) * 256 + kpp;
        uint32_t hi, lo;
        split_pack(acc[nt][0]*inv0, acc[nt][1]*inv0, hi, lo);
        g_aoh[r0] = hi; g_aol[r0] = lo;
        split_pack(acc[nt][2]*inv1, acc[nt][3]*inv1, hi, lo);
        g_aoh[r1] = hi; g_aol[r1] = lo;
    }
}

// ============================================================
extern "C" void kernel_launch(void* const* d_in, const int* in_sizes, int n_in,
                              void* d_out, int out_size)
{
    const float* values = (const float*)d_in[0];
    const float* keys   = (const float*)d_in[1];
    const float* query  = (const float*)d_in[2];
    const int*   mask   = (const int*)  d_in[3];
    const float* Wv     = (const float*)d_in[4];
    const float* Wk     = (const float*)d_in[5];
    const float* Wq     = (const float*)d_in[6];
    const float* Wo     = (const float*)d_in[7];
    const float* bo     = (const float*)d_in[8];

    split_w<<<dim3(EMB*256/256, 4), 256>>>(Wv, Wk, Wq, Wo);
    split_x<<<dim3(NROWS*256/256, 3), 256>>>(values, keys, query);

    cudaFuncSetAttribute(proj_kernel, cudaFuncAttributeMaxDynamicSharedMemorySize, GEMM_SMEM);
    proj_kernel<<<dim3(EMB/128, NROWS/128, 3), 256, GEMM_SMEM>>>();

    cudaFuncSetAttribute(flash_kernel, cudaFuncAttributeMaxDynamicSharedMemorySize, FLASH_SMEM);
    flash_kernel<<<dim3(SEQ/BQF, NH), 256, FLASH_SMEM>>>(mask);

    cudaFuncSetAttribute(out_kernel, cudaFuncAttributeMaxDynamicSharedMemorySize, GEMM_SMEM);
    out_kernel<<<dim3(EMB/128, NROWS/128), 256, GEMM_SMEM>>>(bo, (float*)d_out);
}

// round 8
// speedup vs baseline: 1.0570x; 1.0570x over previous
#include <cuda_runtime.h>
#include <cuda_bf16.h>
#include <stdint.h>

#define N_B   8
#define SEQ   2048
#define EMB   512
#define H     8
#define HD    64
#define NROWS (N_B*SEQ)
#define NH    (N_B*H)

// -------- scratch (no cudaMalloc allowed) --------
// weights: bf16 pairs packed along k: [slot][kp<256][n<512]
__device__ uint32_t g_wh[4*256*EMB], g_wl[4*256*EMB];
// q,k: bf16 pairs packed along d: [(nh*SEQ+s)*32 + dp]
__device__ uint32_t g_qh[(size_t)NH*SEQ*32], g_ql[(size_t)NH*SEQ*32];
__device__ uint32_t g_kh[(size_t)NH*SEQ*32], g_kl[(size_t)NH*SEQ*32];
// v: bf16 pairs packed along s: [(nh*(SEQ/2)+sp)*64 + d]
__device__ uint32_t g_vh[(size_t)NH*(SEQ/2)*64], g_vl[(size_t)NH*(SEQ/2)*64];
__device__ float g_ao[(size_t)NROWS*EMB];

// ---------------- helpers ----------------
__device__ __forceinline__ uint32_t pack2(__nv_bfloat16 a, __nv_bfloat16 b) {
    return ((uint32_t)__bfloat16_as_ushort(b) << 16) | (uint32_t)__bfloat16_as_ushort(a);
}
__device__ __forceinline__ void splitb(float x, __nv_bfloat16 &h, __nv_bfloat16 &l) {
    h = __float2bfloat16_rn(x);
    l = __float2bfloat16_rn(x - __bfloat162float(h));
}
__device__ __forceinline__ void split_pack(float x0, float x1, uint32_t &hi, uint32_t &lo) {
    __nv_bfloat16 h0, l0, h1, l1;
    splitb(x0, h0, l0); splitb(x1, h1, l1);
    hi = pack2(h0, h1); lo = pack2(l0, l1);
}
__device__ __forceinline__ void mmab(float c[4], const uint32_t a[4], const uint32_t b[2]) {
    asm volatile(
      "mma.sync.aligned.m16n8k16.row.col.f32.bf16.bf16.f32 "
      "{%0,%1,%2,%3},{%4,%5,%6,%7},{%8,%9},{%0,%1,%2,%3};\n"
      : "+f"(c[0]), "+f"(c[1]), "+f"(c[2]), "+f"(c[3])
      : "r"(a[0]), "r"(a[1]), "r"(a[2]), "r"(a[3]), "r"(b[0]), "r"(b[1]));
}
__device__ __forceinline__ void cpa16(void* s, const void* g) {
    uint32_t sa = (uint32_t)__cvta_generic_to_shared(s);
    asm volatile("cp.async.cg.shared.global [%0], [%1], 16;" :: "r"(sa), "l"(g) : "memory");
}
#define CPCOMMIT() asm volatile("cp.async.commit_group;" ::: "memory")
#define CPWAIT(n)  asm volatile("cp.async.wait_group %0;" :: "n"(n) : "memory")

// ============================================================
// Pre-split weights -> bf16 hi/lo pairs packed along k.
// ============================================================
__global__ __launch_bounds__(256) void split_w(
    const float* __restrict__ Wv, const float* __restrict__ Wk,
    const float* __restrict__ Wq, const float* __restrict__ Wo)
{
    const int slot = blockIdx.y;
    const float* src = (slot==0)?Wv:(slot==1)?Wk:(slot==2)?Wq:Wo;
    int i = blockIdx.x * 256 + threadIdx.x;      // 0 .. 131071
    int kp = i >> 9, n = i & 511;
    float x0 = src[(2*kp  ) * EMB + n];
    float x1 = src[(2*kp+1) * EMB + n];
    uint32_t hi, lo; split_pack(x0, x1, hi, lo);
    g_wh[(size_t)slot*256*EMB + i] = hi;
    g_wl[(size_t)slot*256*EMB + i] = lo;
}

// ============================================================
// bf16x3 GEMM core: C[128x128] = X(fp32) @ W(pre-split).
// 8 warps 4(m)x2(n), warp tile 32x64, ktile 32, 3-stage ring,
// ONE __syncthreads per k-tile.
// ============================================================
#define AST 36
#define BSTP 136
#define GA (3*128*AST)     // floats
#define GB (3*16*BSTP)     // u32 per array
#define GEMM_SMEM ((GA + 2*GB) * 4)

__device__ __forceinline__ void gemm_prefetch(
    const float* __restrict__ X, const uint32_t* __restrict__ Wh,
    const uint32_t* __restrict__ Wl, float* As, uint32_t* Bh, uint32_t* Bl,
    int m0, int n0, int k0, int buf, int tid)
{
    #pragma unroll
    for (int it = 0; it < 4; it++) {
        int f = tid + 256 * it;
        int row = f >> 3, c4 = f & 7;
        cpa16(&As[(buf*128 + row)*AST + c4*4], X + (size_t)(m0+row)*EMB + k0 + c4*4);
    }
    const int kp0 = k0 >> 1;
    #pragma unroll
    for (int it = 0; it < 2; it++) {
        int f = tid + 256 * it;
        int row = f >> 5, c4 = f & 31;
        cpa16(&Bh[(buf*16 + row)*BSTP + c4*4], Wh + (size_t)(kp0+row)*EMB + n0 + c4*4);
        cpa16(&Bl[(buf*16 + row)*BSTP + c4*4], Wl + (size_t)(kp0+row)*EMB + n0 + c4*4);
    }
}

__device__ __forceinline__ void gemm_core(
    const float* __restrict__ X, const uint32_t* __restrict__ Wh,
    const uint32_t* __restrict__ Wl, float* sm, float c[2][8][4],
    int m0, int n0, int tid)
{
    float* As = sm;
    uint32_t* Bh = (uint32_t*)(sm + GA);
    uint32_t* Bl = Bh + GB;

    const int lane = tid & 31, w = tid >> 5;
    const int g = lane >> 2, cq = lane & 3;
    const int wm = (w & 3) * 32, wn = (w >> 2) * 64;

    #pragma unroll
    for (int mt = 0; mt < 2; mt++)
        #pragma unroll
        for (int nt = 0; nt < 8; nt++)
            #pragma unroll
            for (int e = 0; e < 4; e++) c[mt][nt][e] = 0.f;

    gemm_prefetch(X, Wh, Wl, As, Bh, Bl, m0, n0, 0, 0, tid);
    CPCOMMIT();
    gemm_prefetch(X, Wh, Wl, As, Bh, Bl, m0, n0, 32, 1, tid);
    CPCOMMIT();

    for (int t = 0; t < 16; t++) {
        CPWAIT(1);            // tile t complete (t+1 may be pending)
        __syncthreads();      // visibility + all readers of buf (t+2)%3 done
        if (t + 2 < 16)
            gemm_prefetch(X, Wh, Wl, As, Bh, Bl, m0, n0, (t+2)*32, (t+2)%3, tid);
        CPCOMMIT();           // uniform group accounting (may be empty)

        const int cb = t % 3;
        const int ab = cb * 128, bb = cb * 16;
        #pragma unroll
        for (int ks = 0; ks < 2; ks++) {
            uint32_t ah[2][4], al[2][4];
            #pragma unroll
            for (int mt = 0; mt < 2; mt++) {
                int rb = ab + wm + mt*16 + g;
                int kb = ks*16 + 2*cq;
                float2 v0 = *(const float2*)&As[(rb    )*AST + kb    ];
                float2 v1 = *(const float2*)&As[(rb + 8)*AST + kb    ];
                float2 v2 = *(const float2*)&As[(rb    )*AST + kb + 8];
                float2 v3 = *(const float2*)&As[(rb + 8)*AST + kb + 8];
                split_pack(v0.x, v0.y, ah[mt][0], al[mt][0]);
                split_pack(v1.x, v1.y, ah[mt][1], al[mt][1]);
                split_pack(v2.x, v2.y, ah[mt][2], al[mt][2]);
                split_pack(v3.x, v3.y, ah[mt][3], al[mt][3]);
            }
            uint32_t bh[8][2], bl[8][2];
            #pragma unroll
            for (int nt = 0; nt < 8; nt++) {
                int nn = wn + nt*8 + g;
                int kp = bb + ks*8 + cq;
                bh[nt][0] = Bh[(kp    )*BSTP + nn];
                bh[nt][1] = Bh[(kp + 4)*BSTP + nn];
                bl[nt][0] = Bl[(kp    )*BSTP + nn];
                bl[nt][1] = Bl[(kp + 4)*BSTP + nn];
            }
            #pragma unroll
            for (int mt = 0; mt < 2; mt++)
                #pragma unroll
                for (int nt = 0; nt < 8; nt++) {
                    mmab(c[mt][nt], ah[mt], bh[nt]);
                    mmab(c[mt][nt], al[mt], bh[nt]);
                    mmab(c[mt][nt], ah[mt], bl[nt]);
                }
        }
    }
}

// ============================================================
// Projections. Q: *0.125, d-pair packed. K: d-pair packed.
// V: s-pair packed (transpose pack via shfl).
// ============================================================
__global__ __launch_bounds__(256, 2) void proj_kernel(
    const float* __restrict__ values, const float* __restrict__ keys,
    const float* __restrict__ query)
{
    extern __shared__ float sm[];
    const int which = blockIdx.z;   // 0:v 1:k 2:q
    const float* X = (which == 0) ? values : (which == 1) ? keys : query;
    const uint32_t* Wh = g_wh + (size_t)which * 256 * EMB;
    const uint32_t* Wl = g_wl + (size_t)which * 256 * EMB;

    const int m0 = blockIdx.y * 128, n0 = blockIdx.x * 128;
    float c[2][8][4];
    gemm_core(X, Wh, Wl, sm, c, m0, n0, threadIdx.x);

    const int lane = threadIdx.x & 31, w = threadIdx.x >> 5;
    const int g = lane >> 2, cq = lane & 3;
    const int wm = (w & 3) * 32, wn = (w >> 2) * 64;

    if (which != 0) {
        // Q or K: pack (col, col+1) along d
        uint32_t* dh = (which == 2) ? g_qh : g_kh;
        uint32_t* dl = (which == 2) ? g_ql : g_kl;
        const float post = (which == 2) ? 0.125f : 1.0f;
        #pragma unroll
        for (int mt = 0; mt < 2; mt++)
            #pragma unroll
            for (int half = 0; half < 2; half++) {
                int row = m0 + wm + mt*16 + g + half*8;
                int n = row >> 11, s = row & 2047;
                #pragma unroll
                for (int nt = 0; nt < 8; nt++) {
                    int col = n0 + wn + nt*8 + 2*cq;
                    int h = col >> 6, d = col & 63;
                    size_t base = ((size_t)(n*H + h)*SEQ + s)*32 + (d >> 1);
                    uint32_t hi, lo;
                    split_pack(c[mt][nt][half*2+0]*post, c[mt][nt][half*2+1]*post, hi, lo);
                    dh[base] = hi; dl[base] = lo;
                }
            }
    } else {
        // V: pack (row, row+1) along s via partner exchange
        #pragma unroll
        for (int mt = 0; mt < 2; mt++)
            #pragma unroll
            for (int nt = 0; nt < 8; nt++) {
                float p0 = __shfl_xor_sync(0xffffffffu, c[mt][nt][0], 4);
                float p1 = __shfl_xor_sync(0xffffffffu, c[mt][nt][1], 4);
                float p2 = __shfl_xor_sync(0xffffffffu, c[mt][nt][2], 4);
                float p3 = __shfl_xor_sync(0xffffffffu, c[mt][nt][3], 4);
                if ((g & 1) == 0) {
                    int col = n0 + wn + nt*8 + 2*cq;
                    int h = col >> 6, d = col & 63;
                    #pragma unroll
                    for (int half = 0; half < 2; half++) {
                        int row = m0 + wm + mt*16 + g + half*8;  // even
                        int n = row >> 11, s = row & 2047;
                        size_t base = ((size_t)(n*H + h)*(SEQ/2) + (s >> 1))*64 + d;
                        float m0v = c[mt][nt][half*2+0], m1v = c[mt][nt][half*2+1];
                        float q0v = (half == 0) ? p0 : p2;
                        float q1v = (half == 0) ? p1 : p3;
                        uint32_t h0, l0, h1, l1;
                        split_pack(m0v, q0v, h0, l0);   // (s, s+1) at col d
                        split_pack(m1v, q1v, h1, l1);   // (s, s+1) at col d+1
                        g_vh[base    ] = h0; g_vl[base    ] = l0;
                        g_vh[base + 1] = h1; g_vl[base + 1] = l1;
                    }
                }
            }
    }
}

// ============================================================
// Output GEMM: out = g_ao @ Wo + bo
// ============================================================
__global__ __launch_bounds__(256, 2) void out_kernel(
    const float* __restrict__ bo, float* __restrict__ out)
{
    extern __shared__ float sm[];
    const int m0 = blockIdx.y * 128, n0 = blockIdx.x * 128;
    float c[2][8][4];
    gemm_core(g_ao, g_wh + (size_t)3*256*EMB, g_wl + (size_t)3*256*EMB,
              sm, c, m0, n0, threadIdx.x);

    const int lane = threadIdx.x & 31, w = threadIdx.x >> 5;
    const int g = lane >> 2, cq = lane & 3;
    const int wm = (w & 3) * 32, wn = (w >> 2) * 64;

    #pragma unroll
    for (int mt = 0; mt < 2; mt++)
        #pragma unroll
        for (int half = 0; half < 2; half++) {
            size_t row = m0 + wm + mt*16 + g + half*8;
            #pragma unroll
            for (int nt = 0; nt < 8; nt++) {
                int col = n0 + wn + nt*8 + 2*cq;
                float2 v = make_float2(c[mt][nt][half*2+0] + bo[col],
                                       c[mt][nt][half*2+1] + bo[col+1]);
                *(float2*)&out[row * EMB + col] = v;
            }
        }
}

// ============================================================
// Flash attention, bf16x3. BQ=128, BKV=32, 3-stage ring,
// ONE __syncthreads per kv-tile. 2 CTAs/SM.
// ============================================================
#define BQF 128
#define BKV 32
#define KSTP 36    // u32 stride, 32 dp + pad
#define VSTP 72    // u32 stride, 64 d + pad
#define NT (SEQ/BKV)
#define FK (3*BKV*KSTP)        // u32 per K array
#define FV (3*(BKV/2)*VSTP)    // u32 per V array
#define FL_MS (2*FK + 2*FV)
#define FLASH_SMEM ((FL_MS + 3*BKV) * 4)

__device__ __forceinline__ void flash_prefetch(
    const uint32_t* __restrict__ Khg, const uint32_t* __restrict__ Klg,
    const uint32_t* __restrict__ Vhg, const uint32_t* __restrict__ Vlg,
    const int* __restrict__ mrow, uint32_t* Kh, uint32_t* Kl,
    uint32_t* Vh, uint32_t* Vl, int* ms, int k0, int buf, int tid)
{
    int row = tid >> 3, c4 = tid & 7;          // K: 32 rows x 32 u32
    cpa16(&Kh[(buf*BKV+row)*KSTP + c4*4], Khg + (size_t)(k0+row)*32 + c4*4);
    cpa16(&Kl[(buf*BKV+row)*KSTP + c4*4], Klg + (size_t)(k0+row)*32 + c4*4);
    int vr = tid >> 4, vc = tid & 15;          // V: 16 rows x 64 u32
    cpa16(&Vh[(buf*(BKV/2)+vr)*VSTP + vc*4], Vhg + (size_t)(k0/2+vr)*64 + vc*4);
    cpa16(&Vl[(buf*(BKV/2)+vr)*VSTP + vc*4], Vlg + (size_t)(k0/2+vr)*64 + vc*4);
    if (tid < 8) cpa16(&ms[buf*BKV + tid*4], mrow + k0 + tid*4);
}

__global__ __launch_bounds__(256, 2) void flash_kernel(const int* __restrict__ mask)
{
    extern __shared__ uint32_t smu[];
    uint32_t* Kh = smu;
    uint32_t* Kl = Kh + FK;
    uint32_t* Vh = Kl + FK;
    uint32_t* Vl = Vh + FV;
    int*      ms = (int*)(Vl + FV);

    const int tid = threadIdx.x;
    const int lane = tid & 31, w = tid >> 5;
    const int g = lane >> 2, cq = lane & 3;
    const int q0 = blockIdx.x * BQF;
    const int nh = blockIdx.y;
    const int n = nh >> 3, h = nh & 7;
    const uint32_t* Qhg = g_qh + (size_t)nh * SEQ * 32;
    const uint32_t* Qlg = g_ql + (size_t)nh * SEQ * 32;
    const uint32_t* Khg = g_kh + (size_t)nh * SEQ * 32;
    const uint32_t* Klg = g_kl + (size_t)nh * SEQ * 32;
    const uint32_t* Vhg = g_vh + (size_t)nh * (SEQ/2) * 64;
    const uint32_t* Vlg = g_vl + (size_t)nh * (SEQ/2) * 64;
    const int* mrow = mask + n * SEQ;
    const int rb = w * 16 + g;

    // ---- prefetch kv-tiles 0 and 1 ----
    flash_prefetch(Khg, Klg, Vhg, Vlg, mrow, Kh, Kl, Vh, Vl, ms, 0, 0, tid);
    CPCOMMIT();
    flash_prefetch(Khg, Klg, Vhg, Vlg, mrow, Kh, Kl, Vh, Vl, ms, BKV, 1, tid);
    CPCOMMIT();

    // ---- Q fragments: direct LDG, already split/packed/scaled ----
    uint32_t qh[4][4], ql[4][4];
    {
        const int r0 = q0 + rb, r1 = r0 + 8;
        #pragma unroll
        for (int ks = 0; ks < 4; ks++) {
            int d0 = ks*8 + cq, d1 = ks*8 + 4 + cq;
            qh[ks][0] = Qhg[(size_t)r0*32 + d0];
            qh[ks][1] = Qhg[(size_t)r1*32 + d0];
            qh[ks][2] = Qhg[(size_t)r0*32 + d1];
            qh[ks][3] = Qhg[(size_t)r1*32 + d1];
            ql[ks][0] = Qlg[(size_t)r0*32 + d0];
            ql[ks][1] = Qlg[(size_t)r1*32 + d0];
            ql[ks][2] = Qlg[(size_t)r0*32 + d1];
            ql[ks][3] = Qlg[(size_t)r1*32 + d1];
        }
    }

    float acc[8][4];
    float mi[2] = {-1e30f, -1e30f}, li[2] = {0.f, 0.f};
    #pragma unroll
    for (int nt = 0; nt < 8; nt++)
        #pragma unroll
        for (int e = 0; e < 4; e++) acc[nt][e] = 0.f;

    for (int t = 0; t < NT; t++) {
        CPWAIT(1);            // tile t complete
        __syncthreads();      // visibility + readers of buf (t+2)%3 done
        if (t + 2 < NT)
            flash_prefetch(Khg, Klg, Vhg, Vlg, mrow, Kh, Kl, Vh, Vl, ms,
                           (t+2)*BKV, (t+2)%3, tid);
        CPCOMMIT();

        const int cb = t % 3;
        const uint32_t* KhC = Kh + cb * BKV * KSTP;
        const uint32_t* KlC = Kl + cb * BKV * KSTP;
        const uint32_t* VhC = Vh + cb * (BKV/2) * VSTP;
        const uint32_t* VlC = Vl + cb * (BKV/2) * VSTP;
        const int*      msC = ms + cb * BKV;

        // ---- S = Q @ K^T ----
        float s[4][4];
        #pragma unroll
        for (int nt = 0; nt < 4; nt++)
            #pragma unroll
            for (int e = 0; e < 4; e++) s[nt][e] = 0.f;

        #pragma unroll
        for (int ks = 0; ks < 4; ks++) {
            int d0 = ks*8 + cq, d1 = ks*8 + 4 + cq;
            uint32_t bh[4][2], bl[4][2];
            #pragma unroll
            for (int nt = 0; nt < 4; nt++) {
                int nn = nt*8 + g;
                bh[nt][0] = KhC[nn*KSTP + d0];
                bh[nt][1] = KhC[nn*KSTP + d1];
                bl[nt][0] = KlC[nn*KSTP + d0];
                bl[nt][1] = KlC[nn*KSTP + d1];
            }
            #pragma unroll
            for (int nt = 0; nt < 4; nt++) {
                mmab(s[nt], qh[ks], bh[nt]);
                mmab(s[nt], ql[ks], bh[nt]);
                mmab(s[nt], qh[ks], bl[nt]);
            }
        }

        // ---- mask + online softmax ----
        float mx0 = -1e30f, mx1 = -1e30f;
        #pragma unroll
        for (int nt = 0; nt < 4; nt++) {
            #pragma unroll
            for (int j = 0; j < 2; j++) {
                int mv = msC[nt*8 + 2*cq + j];
                float v0 = mv ? s[nt][j]   : -1e30f;
                float v1 = mv ? s[nt][2+j] : -1e30f;
                s[nt][j] = v0; s[nt][2+j] = v1;
                mx0 = fmaxf(mx0, v0); mx1 = fmaxf(mx1, v1);
            }
        }
        mx0 = fmaxf(mx0, __shfl_xor_sync(0xffffffffu, mx0, 1));
        mx0 = fmaxf(mx0, __shfl_xor_sync(0xffffffffu, mx0, 2));
        mx1 = fmaxf(mx1, __shfl_xor_sync(0xffffffffu, mx1, 1));
        mx1 = fmaxf(mx1, __shfl_xor_sync(0xffffffffu, mx1, 2));

        float mn0 = fmaxf(mi[0], mx0), mn1 = fmaxf(mi[1], mx1);
        float cr0 = __expf(mi[0] - mn0), cr1 = __expf(mi[1] - mn1);
        float sum0 = 0.f, sum1 = 0.f;
        #pragma unroll
        for (int nt = 0; nt < 4; nt++) {
            s[nt][0] = __expf(s[nt][0] - mn0);
            s[nt][1] = __expf(s[nt][1] - mn0);
            s[nt][2] = __expf(s[nt][2] - mn1);
            s[nt][3] = __expf(s[nt][3] - mn1);
            sum0 += s[nt][0] + s[nt][1];
            sum1 += s[nt][2] + s[nt][3];
        }
        sum0 += __shfl_xor_sync(0xffffffffu, sum0, 1);
        sum0 += __shfl_xor_sync(0xffffffffu, sum0, 2);
        sum1 += __shfl_xor_sync(0xffffffffu, sum1, 1);
        sum1 += __shfl_xor_sync(0xffffffffu, sum1, 2);
        li[0] = li[0] * cr0 + sum0; mi[0] = mn0;
        li[1] = li[1] * cr1 + sum1; mi[1] = mn1;
        #pragma unroll
        for (int nt = 0; nt < 8; nt++) {
            acc[nt][0] *= cr0; acc[nt][1] *= cr0;
            acc[nt][2] *= cr1; acc[nt][3] *= cr1;
        }

        // ---- P fragments: register repack (A-frag == C-frag layout) ----
        uint32_t ph[2][4], pl[2][4];
        #pragma unroll
        for (int k2 = 0; k2 < 2; k2++) {
            split_pack(s[2*k2  ][0], s[2*k2  ][1], ph[k2][0], pl[k2][0]);
            split_pack(s[2*k2  ][2], s[2*k2  ][3], ph[k2][1], pl[k2][1]);
            split_pack(s[2*k2+1][0], s[2*k2+1][1], ph[k2][2], pl[k2][2]);
            split_pack(s[2*k2+1][2], s[2*k2+1][3], ph[k2][3], pl[k2][3]);
        }

        // ---- O += P @ V ----
        #pragma unroll
        for (int k2 = 0; k2 < 2; k2++) {
            int sp0 = k2*8 + cq, sp1 = k2*8 + 4 + cq;
            uint32_t vh[8][2], vl[8][2];
            #pragma unroll
            for (int nt = 0; nt < 8; nt++) {
                int dd = nt*8 + g;
                vh[nt][0] = VhC[sp0*VSTP + dd];
                vh[nt][1] = VhC[sp1*VSTP + dd];
                vl[nt][0] = VlC[sp0*VSTP + dd];
                vl[nt][1] = VlC[sp1*VSTP + dd];
            }
            #pragma unroll
            for (int nt = 0; nt < 8; nt++) {
                mmab(acc[nt], ph[k2], vh[nt]);
                mmab(acc[nt], pl[k2], vh[nt]);
                mmab(acc[nt], ph[k2], vl[nt]);
            }
        }
    }

    // ---- epilogue ----
    float inv0 = 1.f / li[0], inv1 = 1.f / li[1];
    #pragma unroll
    for (int nt = 0; nt < 8; nt++) {
        int col = h * 64 + nt * 8 + 2 * cq;
        size_t r0 = (size_t)(n * SEQ + q0 + rb) * EMB + col;
        size_t r1 = (size_t)(n * SEQ + q0 + rb + 8) * EMB + col;
        *(float2*)&g_ao[r0] = make_float2(acc[nt][0]*inv0, acc[nt][1]*inv0);
        *(float2*)&g_ao[r1] = make_float2(acc[nt][2]*inv1, acc[nt][3]*inv1);
    }
}

// ============================================================
extern "C" void kernel_launch(void* const* d_in, const int* in_sizes, int n_in,
                              void* d_out, int out_size)
{
    const float* values = (const float*)d_in[0];
    const float* keys   = (const float*)d_in[1];
    const float* query  = (const float*)d_in[2];
    const int*   mask   = (const int*)  d_in[3];
    const float* Wv     = (const float*)d_in[4];
    const float* Wk     = (const float*)d_in[5];
    const float* Wq     = (const float*)d_in[6];
    const float* Wo     = (const float*)d_in[7];
    const float* bo     = (const float*)d_in[8];

    split_w<<<dim3(EMB*EMB/2/256, 4), 256>>>(Wv, Wk, Wq, Wo);

    cudaFuncSetAttribute(proj_kernel, cudaFuncAttributeMaxDynamicSharedMemorySize, GEMM_SMEM);
    proj_kernel<<<dim3(EMB/128, NROWS/128, 3), 256, GEMM_SMEM>>>(values, keys, query);

    cudaFuncSetAttribute(flash_kernel, cudaFuncAttributeMaxDynamicSharedMemorySize, FLASH_SMEM);
    flash_kernel<<<dim3(SEQ/BQF, NH), 256, FLASH_SMEM>>>(mask);

    cudaFuncSetAttribute(out_kernel, cudaFuncAttributeMaxDynamicSharedMemorySize, GEMM_SMEM);
    out_kernel<<<dim3(EMB/128, NROWS/128), 256, GEMM_SMEM>>>(bo, (float*)d_out);
}

// round 11
// speedup vs baseline: 1.1165x; 1.0564x over previous
#include <cuda_runtime.h>
#include <cuda_bf16.h>
#include <stdint.h>

#define N_B   8
#define SEQ   2048
#define EMB   512
#define H     8
#define HD    64
#define NROWS (N_B*SEQ)
#define NH    (N_B*H)

// -------- scratch (no cudaMalloc allowed) --------
__device__ uint32_t g_wh[4*256*EMB], g_wl[4*256*EMB];
__device__ uint32_t g_qh[(size_t)NH*SEQ*32], g_ql[(size_t)NH*SEQ*32];
__device__ uint32_t g_kh[(size_t)NH*SEQ*32], g_kl[(size_t)NH*SEQ*32];
__device__ uint32_t g_vh[(size_t)NH*(SEQ/2)*64], g_vl[(size_t)NH*(SEQ/2)*64];
__device__ float g_ao[(size_t)NROWS*EMB];

// ---------------- helpers ----------------
__device__ __forceinline__ uint32_t pack2(__nv_bfloat16 a, __nv_bfloat16 b) {
    return ((uint32_t)__bfloat16_as_ushort(b) << 16) | (uint32_t)__bfloat16_as_ushort(a);
}
__device__ __forceinline__ void splitb(float x, __nv_bfloat16 &h, __nv_bfloat16 &l) {
    h = __float2bfloat16_rn(x);
    l = __float2bfloat16_rn(x - __bfloat162float(h));
}
__device__ __forceinline__ void split_pack(float x0, float x1, uint32_t &hi, uint32_t &lo) {
    __nv_bfloat16 h0, l0, h1, l1;
    splitb(x0, h0, l0); splitb(x1, h1, l1);
    hi = pack2(h0, h1); lo = pack2(l0, l1);
}
__device__ __forceinline__ void mmab(float c[4], const uint32_t a[4], const uint32_t b[2]) {
    asm volatile(
      "mma.sync.aligned.m16n8k16.row.col.f32.bf16.bf16.f32 "
      "{%0,%1,%2,%3},{%4,%5,%6,%7},{%8,%9},{%0,%1,%2,%3};\n"
      : "+f"(c[0]), "+f"(c[1]), "+f"(c[2]), "+f"(c[3])
      : "r"(a[0]), "r"(a[1]), "r"(a[2]), "r"(a[3]), "r"(b[0]), "r"(b[1]));
}
__device__ __forceinline__ void cpa16(void* s, const void* g) {
    uint32_t sa = (uint32_t)__cvta_generic_to_shared(s);
    asm volatile("cp.async.cg.shared.global [%0], [%1], 16;" :: "r"(sa), "l"(g) : "memory");
}
__device__ __forceinline__ float ex2f(float x) {
    float r; asm("ex2.approx.ftz.f32 %0, %1;" : "=f"(r) : "f"(x)); return r;
}
#define CPCOMMIT() asm volatile("cp.async.commit_group;" ::: "memory")
#define CPWAIT(n)  asm volatile("cp.async.wait_group %0;" :: "n"(n) : "memory")
// .noinc is load-bearing: without it the async arrive is net-zero on the phase
#define CPA_ARRIVE(a) asm volatile("cp.async.mbarrier.arrive.noinc.shared.b64 [%0];" :: "r"(a) : "memory")
#define MBAR_INIT(a, c)   asm volatile("mbarrier.init.shared.b64 [%0], %1;" :: "r"(a), "r"(c) : "memory")
#define MBAR_ARRIVE(a)    asm volatile("mbarrier.arrive.shared.b64 _, [%0];" :: "r"(a) : "memory")
#define MBAR_WAIT(a, par) do { \
    asm volatile("{\n\t.reg .pred P1;\n\tWL%=:\n\t" \
        "mbarrier.try_wait.parity.acquire.cta.shared::cta.b64 P1, [%0], %1, 0x989680;\n\t" \
        "@P1 bra.uni WD%=;\n\tbra.uni WL%=;\n\tWD%=:\n\t}" \
        :: "r"(a), "r"(par) : "memory"); } while (0)

// ============================================================
// Pre-split weights -> bf16 hi/lo pairs packed along k.
// ============================================================
__global__ __launch_bounds__(256) void split_w(
    const float* __restrict__ Wv, const float* __restrict__ Wk,
    const float* __restrict__ Wq, const float* __restrict__ Wo)
{
    const int slot = blockIdx.y;
    const float* src = (slot==0)?Wv:(slot==1)?Wk:(slot==2)?Wq:Wo;
    int i = blockIdx.x * 256 + threadIdx.x;      // 0 .. 131071
    int kp = i >> 9, n = i & 511;
    float x0 = src[(2*kp  ) * EMB + n];
    float x1 = src[(2*kp+1) * EMB + n];
    uint32_t hi, lo; split_pack(x0, x1, hi, lo);
    g_wh[(size_t)slot*256*EMB + i] = hi;
    g_wl[(size_t)slot*256*EMB + i] = lo;
}

// ============================================================
// bf16x3 GEMM core (R8): ktile 32, 3-stage ring, one sync/tile.
// ============================================================
#define AST 36
#define BSTP 136
#define GA (3*128*AST)
#define GB (3*16*BSTP)
#define GEMM_SMEM ((GA + 2*GB) * 4)

__device__ __forceinline__ void gemm_prefetch(
    const float* __restrict__ X, const uint32_t* __restrict__ Wh,
    const uint32_t* __restrict__ Wl, float* As, uint32_t* Bh, uint32_t* Bl,
    int m0, int n0, int k0, int buf, int tid)
{
    #pragma unroll
    for (int it = 0; it < 4; it++) {
        int f = tid + 256 * it;
        int row = f >> 3, c4 = f & 7;
        cpa16(&As[(buf*128 + row)*AST + c4*4], X + (size_t)(m0+row)*EMB + k0 + c4*4);
    }
    const int kp0 = k0 >> 1;
    #pragma unroll
    for (int it = 0; it < 2; it++) {
        int f = tid + 256 * it;
        int row = f >> 5, c4 = f & 31;
        cpa16(&Bh[(buf*16 + row)*BSTP + c4*4], Wh + (size_t)(kp0+row)*EMB + n0 + c4*4);
        cpa16(&Bl[(buf*16 + row)*BSTP + c4*4], Wl + (size_t)(kp0+row)*EMB + n0 + c4*4);
    }
}

__device__ __forceinline__ void gemm_core(
    const float* __restrict__ X, const uint32_t* __restrict__ Wh,
    const uint32_t* __restrict__ Wl, float* sm, float c[2][8][4],
    int m0, int n0, int tid)
{
    float* As = sm;
    uint32_t* Bh = (uint32_t*)(sm + GA);
    uint32_t* Bl = Bh + GB;

    const int lane = tid & 31, w = tid >> 5;
    const int g = lane >> 2, cq = lane & 3;
    const int wm = (w & 3) * 32, wn = (w >> 2) * 64;

    #pragma unroll
    for (int mt = 0; mt < 2; mt++)
        #pragma unroll
        for (int nt = 0; nt < 8; nt++)
            #pragma unroll
            for (int e = 0; e < 4; e++) c[mt][nt][e] = 0.f;

    gemm_prefetch(X, Wh, Wl, As, Bh, Bl, m0, n0, 0, 0, tid);
    CPCOMMIT();
    gemm_prefetch(X, Wh, Wl, As, Bh, Bl, m0, n0, 32, 1, tid);
    CPCOMMIT();

    for (int t = 0; t < 16; t++) {
        CPWAIT(1);
        __syncthreads();
        if (t + 2 < 16)
            gemm_prefetch(X, Wh, Wl, As, Bh, Bl, m0, n0, (t+2)*32, (t+2)%3, tid);
        CPCOMMIT();

        const int cb = t % 3;
        const int ab = cb * 128, bb = cb * 16;
        #pragma unroll
        for (int ks = 0; ks < 2; ks++) {
            uint32_t ah[2][4], al[2][4];
            #pragma unroll
            for (int mt = 0; mt < 2; mt++) {
                int rb = ab + wm + mt*16 + g;
                int kb = ks*16 + 2*cq;
                float2 v0 = *(const float2*)&As[(rb    )*AST + kb    ];
                float2 v1 = *(const float2*)&As[(rb + 8)*AST + kb    ];
                float2 v2 = *(const float2*)&As[(rb    )*AST + kb + 8];
                float2 v3 = *(const float2*)&As[(rb + 8)*AST + kb + 8];
                split_pack(v0.x, v0.y, ah[mt][0], al[mt][0]);
                split_pack(v1.x, v1.y, ah[mt][1], al[mt][1]);
                split_pack(v2.x, v2.y, ah[mt][2], al[mt][2]);
                split_pack(v3.x, v3.y, ah[mt][3], al[mt][3]);
            }
            uint32_t bh[8][2], bl[8][2];
            #pragma unroll
            for (int nt = 0; nt < 8; nt++) {
                int nn = wn + nt*8 + g;
                int kp = bb + ks*8 + cq;
                bh[nt][0] = Bh[(kp    )*BSTP + nn];
                bh[nt][1] = Bh[(kp + 4)*BSTP + nn];
                bl[nt][0] = Bl[(kp    )*BSTP + nn];
                bl[nt][1] = Bl[(kp + 4)*BSTP + nn];
            }
            #pragma unroll
            for (int mt = 0; mt < 2; mt++)
                #pragma unroll
                for (int nt = 0; nt < 8; nt++) {
                    mmab(c[mt][nt], ah[mt], bh[nt]);
                    mmab(c[mt][nt], al[mt], bh[nt]);
                    mmab(c[mt][nt], ah[mt], bl[nt]);
                }
        }
    }
}

// ============================================================
// Projections. Q: *0.125*log2(e) (exp2 softmax), d-pair packed.
// K: d-pair packed. V: s-pair packed via shfl.
// ============================================================
__global__ __launch_bounds__(256, 2) void proj_kernel(
    const float* __restrict__ values, const float* __restrict__ keys,
    const float* __restrict__ query)
{
    extern __shared__ float sm[];
    const int which = blockIdx.z;   // 0:v 1:k 2:q
    const float* X = (which == 0) ? values : (which == 1) ? keys : query;
    const uint32_t* Wh = g_wh + (size_t)which * 256 * EMB;
    const uint32_t* Wl = g_wl + (size_t)which * 256 * EMB;

    const int m0 = blockIdx.y * 128, n0 = blockIdx.x * 128;
    float c[2][8][4];
    gemm_core(X, Wh, Wl, sm, c, m0, n0, threadIdx.x);

    const int lane = threadIdx.x & 31, w = threadIdx.x >> 5;
    const int g = lane >> 2, cq = lane & 3;
    const int wm = (w & 3) * 32, wn = (w >> 2) * 64;

    if (which != 0) {
        uint32_t* dh = (which == 2) ? g_qh : g_kh;
        uint32_t* dl = (which == 2) ? g_ql : g_kl;
        const float post = (which == 2) ? 0.125f * 1.44269504f : 1.0f;
        #pragma unroll
        for (int mt = 0; mt < 2; mt++)
            #pragma unroll
            for (int half = 0; half < 2; half++) {
                int row = m0 + wm + mt*16 + g + half*8;
                int n = row >> 11, s = row & 2047;
                #pragma unroll
                for (int nt = 0; nt < 8; nt++) {
                    int col = n0 + wn + nt*8 + 2*cq;
                    int h = col >> 6, d = col & 63;
                    size_t base = ((size_t)(n*H + h)*SEQ + s)*32 + (d >> 1);
                    uint32_t hi, lo;
                    split_pack(c[mt][nt][half*2+0]*post, c[mt][nt][half*2+1]*post, hi, lo);
                    dh[base] = hi; dl[base] = lo;
                }
            }
    } else {
        #pragma unroll
        for (int mt = 0; mt < 2; mt++)
            #pragma unroll
            for (int nt = 0; nt < 8; nt++) {
                float p0 = __shfl_xor_sync(0xffffffffu, c[mt][nt][0], 4);
                float p1 = __shfl_xor_sync(0xffffffffu, c[mt][nt][1], 4);
                float p2 = __shfl_xor_sync(0xffffffffu, c[mt][nt][2], 4);
                float p3 = __shfl_xor_sync(0xffffffffu, c[mt][nt][3], 4);
                if ((g & 1) == 0) {
                    int col = n0 + wn + nt*8 + 2*cq;
                    int h = col >> 6, d = col & 63;
                    #pragma unroll
                    for (int half = 0; half < 2; half++) {
                        int row = m0 + wm + mt*16 + g + half*8;  // even
                        int n = row >> 11, s = row & 2047;
                        size_t base = ((size_t)(n*H + h)*(SEQ/2) + (s >> 1))*64 + d;
                        float m0v = c[mt][nt][half*2+0], m1v = c[mt][nt][half*2+1];
                        float q0v = (half == 0) ? p0 : p2;
                        float q1v = (half == 0) ? p1 : p3;
                        uint32_t h0, l0, h1, l1;
                        split_pack(m0v, q0v, h0, l0);
                        split_pack(m1v, q1v, h1, l1);
                        g_vh[base    ] = h0; g_vl[base    ] = l0;
                        g_vh[base + 1] = h1; g_vl[base + 1] = l1;
                    }
                }
            }
    }
}

// ============================================================
// Output GEMM: out = g_ao @ Wo + bo
// ============================================================
__global__ __launch_bounds__(256, 2) void out_kernel(
    const float* __restrict__ bo, float* __restrict__ out)
{
    extern __shared__ float sm[];
    const int m0 = blockIdx.y * 128, n0 = blockIdx.x * 128;
    float c[2][8][4];
    gemm_core(g_ao, g_wh + (size_t)3*256*EMB, g_wl + (size_t)3*256*EMB,
              sm, c, m0, n0, threadIdx.x);

    const int lane = threadIdx.x & 31, w = threadIdx.x >> 5;
    const int g = lane >> 2, cq = lane & 3;
    const int wm = (w & 3) * 32, wn = (w >> 2) * 64;

    #pragma unroll
    for (int mt = 0; mt < 2; mt++)
        #pragma unroll
        for (int half = 0; half < 2; half++) {
            size_t row = m0 + wm + mt*16 + g + half*8;
            #pragma unroll
            for (int nt = 0; nt < 8; nt++) {
                int col = n0 + wn + nt*8 + 2*cq;
                float2 v = make_float2(c[mt][nt][half*2+0] + bo[col],
                                       c[mt][nt][half*2+1] + bo[col+1]);
                *(float2*)&out[row * EMB + col] = v;
            }
        }
}

// ============================================================
// Flash attention, bf16x3, BQ=128, BKV=32, 4-stage mbarrier
// pipeline with per-warp drift — NO __syncthreads in loop.
// ============================================================
#define BQF 128
#define BKV 32
#define SFL 4
#define KSTP 36
#define VSTP 72
#define NT (SEQ/BKV)
#define FK (SFL*BKV*KSTP)
#define FV (SFL*(BKV/2)*VSTP)
#define FL_MS (2*FK + 2*FV)
#define FL_MB (FL_MS + SFL*BKV)
#define FLASH_SMEM (FL_MB*4 + 64)

__device__ __forceinline__ void flash_fill(
    const uint32_t* __restrict__ Khg, const uint32_t* __restrict__ Klg,
    const uint32_t* __restrict__ Vhg, const uint32_t* __restrict__ Vlg,
    const int* __restrict__ mrow, uint32_t* Kh, uint32_t* Kl,
    uint32_t* Vh, uint32_t* Vl, int* ms, int k0, int buf, int tid)
{
    int row = tid >> 3, c4 = tid & 7;
    cpa16(&Kh[(buf*BKV+row)*KSTP + c4*4], Khg + (size_t)(k0+row)*32 + c4*4);
    cpa16(&Kl[(buf*BKV+row)*KSTP + c4*4], Klg + (size_t)(k0+row)*32 + c4*4);
    int vr = tid >> 4, vc = tid & 15;
    cpa16(&Vh[(buf*(BKV/2)+vr)*VSTP + vc*4], Vhg + (size_t)(k0/2+vr)*64 + vc*4);
    cpa16(&Vl[(buf*(BKV/2)+vr)*VSTP + vc*4], Vlg + (size_t)(k0/2+vr)*64 + vc*4);
    if (tid < 8) cpa16(&ms[buf*BKV + tid*4], mrow + k0 + tid*4);
}

__global__ __launch_bounds__(256, 2) void flash_kernel(const int* __restrict__ mask)
{
    extern __shared__ uint32_t smu[];
    uint32_t* Kh = smu;
    uint32_t* Kl = Kh + FK;
    uint32_t* Vh = Kl + FK;
    uint32_t* Vl = Vh + FV;
    int*      ms = (int*)(smu + FL_MS);
    const uint32_t sbF = (uint32_t)__cvta_generic_to_shared(smu);
    const uint32_t mb1 = sbF + FL_MB*4;
    const uint32_t mb2 = sbF + FL_MB*4 + 32;

    const int tid = threadIdx.x;
    const int lane = tid & 31, w = tid >> 5;
    const int g = lane >> 2, cq = lane & 3;
    const int q0 = blockIdx.x * BQF;
    const int nh = blockIdx.y;
    const int n = nh >> 3, h = nh & 7;
    const uint32_t* Qhg = g_qh + (size_t)nh * SEQ * 32;
    const uint32_t* Qlg = g_ql + (size_t)nh * SEQ * 32;
    const uint32_t* Khg = g_kh + (size_t)nh * SEQ * 32;
    const uint32_t* Klg = g_kl + (size_t)nh * SEQ * 32;
    const uint32_t* Vhg = g_vh + (size_t)nh * (SEQ/2) * 64;
    const uint32_t* Vlg = g_vl + (size_t)nh * (SEQ/2) * 64;
    const int* mrow = mask + n * SEQ;
    const int rb = w * 16 + g;

    if (tid == 0) {
        #pragma unroll
        for (int s = 0; s < SFL; s++) {
            MBAR_INIT(mb1 + s*8, 256);
            MBAR_INIT(mb2 + s*8, 256);
        }
    }
    __syncthreads();

    flash_fill(Khg, Klg, Vhg, Vlg, mrow, Kh, Kl, Vh, Vl, ms, 0, 0, tid);
    CPA_ARRIVE(mb1 + 0*8);
    flash_fill(Khg, Klg, Vhg, Vlg, mrow, Kh, Kl, Vh, Vl, ms, BKV, 1, tid);
    CPA_ARRIVE(mb1 + 1*8);

    uint32_t qh[4][4], ql[4][4];
    {
        const int r0 = q0 + rb, r1 = r0 + 8;
        #pragma unroll
        for (int ks = 0; ks < 4; ks++) {
            int d0 = ks*8 + cq, d1 = ks*8 + 4 + cq;
            qh[ks][0] = Qhg[(size_t)r0*32 + d0];
            qh[ks][1] = Qhg[(size_t)r1*32 + d0];
            qh[ks][2] = Qhg[(size_t)r0*32 + d1];
            qh[ks][3] = Qhg[(size_t)r1*32 + d1];
            ql[ks][0] = Qlg[(size_t)r0*32 + d0];
            ql[ks][1] = Qlg[(size_t)r1*32 + d0];
            ql[ks][2] = Qlg[(size_t)r0*32 + d1];
            ql[ks][3] = Qlg[(size_t)r1*32 + d1];
        }
    }

    float acc[8][4];
    float mi[2] = {-1e30f, -1e30f}, li[2] = {0.f, 0.f};
    #pragma unroll
    for (int nt = 0; nt < 8; nt++)
        #pragma unroll
        for (int e = 0; e < 4; e++) acc[nt][e] = 0.f;

    for (int t = 0; t < NT; t++) {
        const int f = t + 2;
        if (f < NT) {
            const int s = f & 3;
            if (t >= 2) MBAR_WAIT(mb2 + s*8, ((t - 2) >> 2) & 1);
            flash_fill(Khg, Klg, Vhg, Vlg, mrow, Kh, Kl, Vh, Vl, ms, f*BKV, s, tid);
            CPA_ARRIVE(mb1 + s*8);
        }

        const int cb = t & 3;
        MBAR_WAIT(mb1 + cb*8, (t >> 2) & 1);

        const uint32_t* KhC = Kh + cb * BKV * KSTP;
        const uint32_t* KlC = Kl + cb * BKV * KSTP;
        const uint32_t* VhC = Vh + cb * (BKV/2) * VSTP;
        const uint32_t* VlC = Vl + cb * (BKV/2) * VSTP;
        const int*      msC = ms + cb * BKV;

        float s[4][4];
        #pragma unroll
        for (int nt = 0; nt < 4; nt++)
            #pragma unroll
            for (int e = 0; e < 4; e++) s[nt][e] = 0.f;

        #pragma unroll
        for (int ks = 0; ks < 4; ks++) {
            int d0 = ks*8 + cq, d1 = ks*8 + 4 + cq;
            uint32_t bh[4][2], bl[4][2];
            #pragma unroll
            for (int nt = 0; nt < 4; nt++) {
                int nn = nt*8 + g;
                bh[nt][0] = KhC[nn*KSTP + d0];
                bh[nt][1] = KhC[nn*KSTP + d1];
                bl[nt][0] = KlC[nn*KSTP + d0];
                bl[nt][1] = KlC[nn*KSTP + d1];
            }
            #pragma unroll
            for (int nt = 0; nt < 4; nt++) {
                mmab(s[nt], qh[ks], bh[nt]);
                mmab(s[nt], ql[ks], bh[nt]);
                mmab(s[nt], qh[ks], bl[nt]);
            }
        }

        float mx0 = -1e30f, mx1 = -1e30f;
        #pragma unroll
        for (int nt = 0; nt < 4; nt++) {
            #pragma unroll
            for (int j = 0; j < 2; j++) {
                int mv = msC[nt*8 + 2*cq + j];
                float v0 = mv ? s[nt][j]   : -1e30f;
                float v1 = mv ? s[nt][2+j] : -1e30f;
                s[nt][j] = v0; s[nt][2+j] = v1;
                mx0 = fmaxf(mx0, v0); mx1 = fmaxf(mx1, v1);
            }
        }
        mx0 = fmaxf(mx0, __shfl_xor_sync(0xffffffffu, mx0, 1));
        mx0 = fmaxf(mx0, __shfl_xor_sync(0xffffffffu, mx0, 2));
        mx1 = fmaxf(mx1, __shfl_xor_sync(0xffffffffu, mx1, 1));
        mx1 = fmaxf(mx1, __shfl_xor_sync(0xffffffffu, mx1, 2));

        float mn0 = fmaxf(mi[0], mx0), mn1 = fmaxf(mi[1], mx1);
        float cr0 = ex2f(mi[0] - mn0), cr1 = ex2f(mi[1] - mn1);
        float sum0 = 0.f, sum1 = 0.f;
        #pragma unroll
        for (int nt = 0; nt < 4; nt++) {
            s[nt][0] = ex2f(s[nt][0] - mn0);
            s[nt][1] = ex2f(s[nt][1] - mn0);
            s[nt][2] = ex2f(s[nt][2] - mn1);
            s[nt][3] = ex2f(s[nt][3] - mn1);
            sum0 += s[nt][0] + s[nt][1];
            sum1 += s[nt][2] + s[nt][3];
        }
        sum0 += __shfl_xor_sync(0xffffffffu, sum0, 1);
        sum0 += __shfl_xor_sync(0xffffffffu, sum0, 2);
        sum1 += __shfl_xor_sync(0xffffffffu, sum1, 1);
        sum1 += __shfl_xor_sync(0xffffffffu, sum1, 2);
        li[0] = li[0] * cr0 + sum0; mi[0] = mn0;
        li[1] = li[1] * cr1 + sum1; mi[1] = mn1;
        #pragma unroll
        for (int nt = 0; nt < 8; nt++) {
            acc[nt][0] *= cr0; acc[nt][1] *= cr0;
            acc[nt][2] *= cr1; acc[nt][3] *= cr1;
        }

        uint32_t ph[2][4], pl[2][4];
        #pragma unroll
        for (int k2 = 0; k2 < 2; k2++) {
            split_pack(s[2*k2  ][0], s[2*k2  ][1], ph[k2][0], pl[k2][0]);
            split_pack(s[2*k2  ][2], s[2*k2  ][3], ph[k2][1], pl[k2][1]);
            split_pack(s[2*k2+1][0], s[2*k2+1][1], ph[k2][2], pl[k2][2]);
            split_pack(s[2*k2+1][2], s[2*k2+1][3], ph[k2][3], pl[k2][3]);
        }

        #pragma unroll
        for (int k2 = 0; k2 < 2; k2++) {
            int sp0 = k2*8 + cq, sp1 = k2*8 + 4 + cq;
            uint32_t vh[8][2], vl[8][2];
            #pragma unroll
            for (int nt = 0; nt < 8; nt++) {
                int dd = nt*8 + g;
                vh[nt][0] = VhC[sp0*VSTP + dd];
                vh[nt][1] = VhC[sp1*VSTP + dd];
                vl[nt][0] = VlC[sp0*VSTP + dd];
                vl[nt][1] = VlC[sp1*VSTP + dd];
            }
            #pragma unroll
            for (int nt = 0; nt < 8; nt++) {
                mmab(acc[nt], ph[k2], vh[nt]);
                mmab(acc[nt], pl[k2], vh[nt]);
                mmab(acc[nt], ph[k2], vl[nt]);
            }
        }

        MBAR_ARRIVE(mb2 + cb*8);
    }

    float inv0 = 1.f / li[0], inv1 = 1.f / li[1];
    #pragma unroll
    for (int nt = 0; nt < 8; nt++) {
        int col = h * 64 + nt * 8 + 2 * cq;
        size_t r0 = (size_t)(n * SEQ + q0 + rb) * EMB + col;
        size_t r1 = (size_t)(n * SEQ + q0 + rb + 8) * EMB + col;
        *(float2*)&g_ao[r0] = make_float2(acc[nt][0]*inv0, acc[nt][1]*inv0);
        *(float2*)&g_ao[r1] = make_float2(acc[nt][2]*inv1, acc[nt][3]*inv1);
    }
}

// ============================================================
extern "C" void kernel_launch(void* const* d_in, const int* in_sizes, int n_in,
                              void* d_out, int out_size)
{
    const float* values = (const float*)d_in[0];
    const float* keys   = (const float*)d_in[1];
    const float* query  = (const float*)d_in[2];
    const int*   mask   = (const int*)  d_in[3];
    const float* Wv     = (const float*)d_in[4];
    const float* Wk     = (const float*)d_in[5];
    const float* Wq     = (const float*)d_in[6];
    const float* Wo     = (const float*)d_in[7];
    const float* bo     = (const float*)d_in[8];

    split_w<<<dim3(EMB*EMB/2/256, 4), 256>>>(Wv, Wk, Wq, Wo);

    cudaFuncSetAttribute(proj_kernel, cudaFuncAttributeMaxDynamicSharedMemorySize, GEMM_SMEM);
    proj_kernel<<<dim3(EMB/128, NROWS/128, 3), 256, GEMM_SMEM>>>(values, keys, query);

    cudaFuncSetAttribute(flash_kernel, cudaFuncAttributeMaxDynamicSharedMemorySize, FLASH_SMEM);
    flash_kernel<<<dim3(SEQ/BQF, NH), 256, FLASH_SMEM>>>(mask);

    cudaFuncSetAttribute(out_kernel, cudaFuncAttributeMaxDynamicSharedMemorySize, GEMM_SMEM);
    out_kernel<<<dim3(EMB/128, NROWS/128), 256, GEMM_SMEM>>>(bo, (float*)d_out);
}

// round 12
// speedup vs baseline: 1.4963x; 1.3401x over previous
#include <cuda_runtime.h>
#include <cuda_fp16.h>
#include <stdint.h>

#define N_B   8
#define SEQ   2048
#define EMB   512
#define H     8
#define HD    64
#define NROWS (N_B*SEQ)
#define NH    (N_B*H)

// -------- scratch (no cudaMalloc allowed) --------
// weights hi-only: fp16 pairs packed along k: [slot][kp<256][n<512]
__device__ uint32_t g_wh[4*256*EMB];
// q: hi+lo fp16 pairs packed along d; k: hi only
__device__ uint32_t g_qh[(size_t)NH*SEQ*32], g_ql[(size_t)NH*SEQ*32];
__device__ uint32_t g_kh[(size_t)NH*SEQ*32];
// v hi only: fp16 pairs packed along s: [(nh*(SEQ/2)+sp)*64 + d]
__device__ uint32_t g_vh[(size_t)NH*(SEQ/2)*64];
__device__ float g_ao[(size_t)NROWS*EMB];

// ---------------- helpers ----------------
__device__ __forceinline__ uint32_t pack2h(__half a, __half b) {
    return ((uint32_t)__half_as_ushort(b) << 16) | (uint32_t)__half_as_ushort(a);
}
__device__ __forceinline__ void split_packh(float x0, float x1, uint32_t &hi, uint32_t &lo) {
    __half h0 = __float2half_rn(x0), h1 = __float2half_rn(x1);
    __half l0 = __float2half_rn(x0 - __half2float(h0));
    __half l1 = __float2half_rn(x1 - __half2float(h1));
    hi = pack2h(h0, h1); lo = pack2h(l0, l1);
}
__device__ __forceinline__ uint32_t packh_hi(float x0, float x1) {
    return pack2h(__float2half_rn(x0), __float2half_rn(x1));
}
__device__ __forceinline__ void mmah(float c[4], const uint32_t a[4], const uint32_t b[2]) {
    asm volatile(
      "mma.sync.aligned.m16n8k16.row.col.f32.f16.f16.f32 "
      "{%0,%1,%2,%3},{%4,%5,%6,%7},{%8,%9},{%0,%1,%2,%3};\n"
      : "+f"(c[0]), "+f"(c[1]), "+f"(c[2]), "+f"(c[3])
      : "r"(a[0]), "r"(a[1]), "r"(a[2]), "r"(a[3]), "r"(b[0]), "r"(b[1]));
}
__device__ __forceinline__ void cpa16(void* s, const void* g) {
    uint32_t sa = (uint32_t)__cvta_generic_to_shared(s);
    asm volatile("cp.async.cg.shared.global [%0], [%1], 16;" :: "r"(sa), "l"(g) : "memory");
}
__device__ __forceinline__ float ex2f(float x) {
    float r; asm("ex2.approx.ftz.f32 %0, %1;" : "=f"(r) : "f"(x)); return r;
}
#define CPCOMMIT() asm volatile("cp.async.commit_group;" ::: "memory")
#define CPWAIT(n)  asm volatile("cp.async.wait_group %0;" :: "n"(n) : "memory")
#define CPA_ARRIVE(a) asm volatile("cp.async.mbarrier.arrive.noinc.shared.b64 [%0];" :: "r"(a) : "memory")
#define MBAR_INIT(a, c)   asm volatile("mbarrier.init.shared.b64 [%0], %1;" :: "r"(a), "r"(c) : "memory")
#define MBAR_ARRIVE(a)    asm volatile("mbarrier.arrive.shared.b64 _, [%0];" :: "r"(a) : "memory")
#define MBAR_WAIT(a, par) do { \
    asm volatile("{\n\t.reg .pred P1;\n\tWL%=:\n\t" \
        "mbarrier.try_wait.parity.acquire.cta.shared::cta.b64 P1, [%0], %1, 0x989680;\n\t" \
        "@P1 bra.uni WD%=;\n\tbra.uni WL%=;\n\tWD%=:\n\t}" \
        :: "r"(a), "r"(par) : "memory"); } while (0)

// ============================================================
// Pre-split weights -> fp16 hi pairs packed along k (hi only;
// A-side carries the lo term: C = (xh+xl)·wh, err = x·wl ~2^-12)
// ============================================================
__global__ __launch_bounds__(256) void split_w(
    const float* __restrict__ Wv, const float* __restrict__ Wk,
    const float* __restrict__ Wq, const float* __restrict__ Wo)
{
    const int slot = blockIdx.y;
    const float* src = (slot==0)?Wv:(slot==1)?Wk:(slot==2)?Wq:Wo;
    int i = blockIdx.x * 256 + threadIdx.x;      // 0 .. 131071
    int kp = i >> 9, n = i & 511;
    float x0 = src[(2*kp  ) * EMB + n];
    float x1 = src[(2*kp+1) * EMB + n];
    g_wh[(size_t)slot*256*EMB + i] = packh_hi(x0, x1);
}

// ============================================================
// fp16x2 GEMM core: ktile 32, 3-stage ring, one sync/tile.
// A split inline (hi+lo), B hi-only.
// ============================================================
#define AST 36
#define BSTP 136
#define GA (3*128*AST)     // floats
#define GB (3*16*BSTP)     // u32 (hi only)
#define GEMM_SMEM ((GA + GB) * 4)

__device__ __forceinline__ void gemm_prefetch(
    const float* __restrict__ X, const uint32_t* __restrict__ Wh,
    float* As, uint32_t* Bh, int m0, int n0, int k0, int buf, int tid)
{
    #pragma unroll
    for (int it = 0; it < 4; it++) {
        int f = tid + 256 * it;
        int row = f >> 3, c4 = f & 7;
        cpa16(&As[(buf*128 + row)*AST + c4*4], X + (size_t)(m0+row)*EMB + k0 + c4*4);
    }
    const int kp0 = k0 >> 1;
    #pragma unroll
    for (int it = 0; it < 2; it++) {
        int f = tid + 256 * it;
        int row = f >> 5, c4 = f & 31;
        cpa16(&Bh[(buf*16 + row)*BSTP + c4*4], Wh + (size_t)(kp0+row)*EMB + n0 + c4*4);
    }
}

__device__ __forceinline__ void gemm_core(
    const float* __restrict__ X, const uint32_t* __restrict__ Wh,
    float* sm, float c[2][8][4], int m0, int n0, int tid)
{
    float* As = sm;
    uint32_t* Bh = (uint32_t*)(sm + GA);

    const int lane = tid & 31, w = tid >> 5;
    const int g = lane >> 2, cq = lane & 3;
    const int wm = (w & 3) * 32, wn = (w >> 2) * 64;

    #pragma unroll
    for (int mt = 0; mt < 2; mt++)
        #pragma unroll
        for (int nt = 0; nt < 8; nt++)
            #pragma unroll
            for (int e = 0; e < 4; e++) c[mt][nt][e] = 0.f;

    gemm_prefetch(X, Wh, As, Bh, m0, n0, 0, 0, tid);
    CPCOMMIT();
    gemm_prefetch(X, Wh, As, Bh, m0, n0, 32, 1, tid);
    CPCOMMIT();

    for (int t = 0; t < 16; t++) {
        CPWAIT(1);
        __syncthreads();
        if (t + 2 < 16)
            gemm_prefetch(X, Wh, As, Bh, m0, n0, (t+2)*32, (t+2)%3, tid);
        CPCOMMIT();

        const int cb = t % 3;
        const int ab = cb * 128, bb = cb * 16;
        #pragma unroll
        for (int ks = 0; ks < 2; ks++) {
            uint32_t ah[2][4], al[2][4];
            #pragma unroll
            for (int mt = 0; mt < 2; mt++) {
                int rb = ab + wm + mt*16 + g;
                int kb = ks*16 + 2*cq;
                float2 v0 = *(const float2*)&As[(rb    )*AST + kb    ];
                float2 v1 = *(const float2*)&As[(rb + 8)*AST + kb    ];
                float2 v2 = *(const float2*)&As[(rb    )*AST + kb + 8];
                float2 v3 = *(const float2*)&As[(rb + 8)*AST + kb + 8];
                split_packh(v0.x, v0.y, ah[mt][0], al[mt][0]);
                split_packh(v1.x, v1.y, ah[mt][1], al[mt][1]);
                split_packh(v2.x, v2.y, ah[mt][2], al[mt][2]);
                split_packh(v3.x, v3.y, ah[mt][3], al[mt][3]);
            }
            uint32_t bh[8][2];
            #pragma unroll
            for (int nt = 0; nt < 8; nt++) {
                int nn = wn + nt*8 + g;
                int kp = bb + ks*8 + cq;
                bh[nt][0] = Bh[(kp    )*BSTP + nn];
                bh[nt][1] = Bh[(kp + 4)*BSTP + nn];
            }
            #pragma unroll
            for (int mt = 0; mt < 2; mt++)
                #pragma unroll
                for (int nt = 0; nt < 8; nt++) {
                    mmah(c[mt][nt], ah[mt], bh[nt]);
                    mmah(c[mt][nt], al[mt], bh[nt]);
                }
        }
    }
}

// ============================================================
// Projections. Q: *0.125*log2(e), hi+lo d-pair packed.
// K: hi only d-pair packed. V: hi only s-pair packed via shfl.
// ============================================================
__global__ __launch_bounds__(256, 2) void proj_kernel(
    const float* __restrict__ values, const float* __restrict__ keys,
    const float* __restrict__ query)
{
    extern __shared__ float sm[];
    const int which = blockIdx.z;   // 0:v 1:k 2:q
    const float* X = (which == 0) ? values : (which == 1) ? keys : query;
    const uint32_t* Wh = g_wh + (size_t)which * 256 * EMB;

    const int m0 = blockIdx.y * 128, n0 = blockIdx.x * 128;
    float c[2][8][4];
    gemm_core(X, Wh, sm, c, m0, n0, threadIdx.x);

    const int lane = threadIdx.x & 31, w = threadIdx.x >> 5;
    const int g = lane >> 2, cq = lane & 3;
    const int wm = (w & 3) * 32, wn = (w >> 2) * 64;

    if (which == 2) {
        // Q: hi+lo, pre-scaled for exp2-domain softmax
        const float post = 0.125f * 1.44269504f;
        #pragma unroll
        for (int mt = 0; mt < 2; mt++)
            #pragma unroll
            for (int half = 0; half < 2; half++) {
                int row = m0 + wm + mt*16 + g + half*8;
                int n = row >> 11, s = row & 2047;
                #pragma unroll
                for (int nt = 0; nt < 8; nt++) {
                    int col = n0 + wn + nt*8 + 2*cq;
                    int h = col >> 6, d = col & 63;
                    size_t base = ((size_t)(n*H + h)*SEQ + s)*32 + (d >> 1);
                    uint32_t hi, lo;
                    split_packh(c[mt][nt][half*2+0]*post, c[mt][nt][half*2+1]*post, hi, lo);
                    g_qh[base] = hi; g_ql[base] = lo;
                }
            }
    } else if (which == 1) {
        // K: hi only
        #pragma unroll
        for (int mt = 0; mt < 2; mt++)
            #pragma unroll
            for (int half = 0; half < 2; half++) {
                int row = m0 + wm + mt*16 + g + half*8;
                int n = row >> 11, s = row & 2047;
                #pragma unroll
                for (int nt = 0; nt < 8; nt++) {
                    int col = n0 + wn + nt*8 + 2*cq;
                    int h = col >> 6, d = col & 63;
                    size_t base = ((size_t)(n*H + h)*SEQ + s)*32 + (d >> 1);
                    g_kh[base] = packh_hi(c[mt][nt][half*2+0], c[mt][nt][half*2+1]);
                }
            }
    } else {
        // V: hi only, s-pair packed via partner exchange
        #pragma unroll
        for (int mt = 0; mt < 2; mt++)
            #pragma unroll
            for (int nt = 0; nt < 8; nt++) {
                float p0 = __shfl_xor_sync(0xffffffffu, c[mt][nt][0], 4);
                float p1 = __shfl_xor_sync(0xffffffffu, c[mt][nt][1], 4);
                float p2 = __shfl_xor_sync(0xffffffffu, c[mt][nt][2], 4);
                float p3 = __shfl_xor_sync(0xffffffffu, c[mt][nt][3], 4);
                if ((g & 1) == 0) {
                    int col = n0 + wn + nt*8 + 2*cq;
                    int h = col >> 6, d = col & 63;
                    #pragma unroll
                    for (int half = 0; half < 2; half++) {
                        int row = m0 + wm + mt*16 + g + half*8;  // even
                        int n = row >> 11, s = row & 2047;
                        size_t base = ((size_t)(n*H + h)*(SEQ/2) + (s >> 1))*64 + d;
                        float m0v = c[mt][nt][half*2+0], m1v = c[mt][nt][half*2+1];
                        float q0v = (half == 0) ? p0 : p2;
                        float q1v = (half == 0) ? p1 : p3;
                        g_vh[base    ] = packh_hi(m0v, q0v);   // (s, s+1) at col d
                        g_vh[base + 1] = packh_hi(m1v, q1v);   // (s, s+1) at col d+1
                    }
                }
            }
    }
}

// ============================================================
// Output GEMM: out = g_ao @ Wo + bo
// ============================================================
__global__ __launch_bounds__(256, 2) void out_kernel(
    const float* __restrict__ bo, float* __restrict__ out)
{
    extern __shared__ float sm[];
    const int m0 = blockIdx.y * 128, n0 = blockIdx.x * 128;
    float c[2][8][4];
    gemm_core(g_ao, g_wh + (size_t)3*256*EMB, sm, c, m0, n0, threadIdx.x);

    const int lane = threadIdx.x & 31, w = threadIdx.x >> 5;
    const int g = lane >> 2, cq = lane & 3;
    const int wm = (w & 3) * 32, wn = (w >> 2) * 64;

    #pragma unroll
    for (int mt = 0; mt < 2; mt++)
        #pragma unroll
        for (int half = 0; half < 2; half++) {
            size_t row = m0 + wm + mt*16 + g + half*8;
            #pragma unroll
            for (int nt = 0; nt < 8; nt++) {
                int col = n0 + wn + nt*8 + 2*cq;
                float2 v = make_float2(c[mt][nt][half*2+0] + bo[col],
                                       c[mt][nt][half*2+1] + bo[col+1]);
                *(float2*)&out[row * EMB + col] = v;
            }
        }
}

// ============================================================
// Flash attention, fp16x2, BQ=128, BKV=32, 4-stage mbarrier
// pipeline, no __syncthreads in loop. K/V hi-only.
// ============================================================
#define BQF 128
#define BKV 32
#define SFL 4
#define KSTP 36
#define VSTP 72
#define NT (SEQ/BKV)
#define FK (SFL*BKV*KSTP)        // 4608 u32
#define FV (SFL*(BKV/2)*VSTP)    // 4608 u32
#define FL_MS (FK + FV)
#define FL_MB (FL_MS + SFL*BKV)
#define FLASH_SMEM (FL_MB*4 + 64)

__device__ __forceinline__ void flash_fill(
    const uint32_t* __restrict__ Khg, const uint32_t* __restrict__ Vhg,
    const int* __restrict__ mrow, uint32_t* Kh, uint32_t* Vh,
    int* ms, int k0, int buf, int tid)
{
    int row = tid >> 3, c4 = tid & 7;          // K: 32 rows x 32 u32
    cpa16(&Kh[(buf*BKV+row)*KSTP + c4*4], Khg + (size_t)(k0+row)*32 + c4*4);
    int vr = tid >> 4, vc = tid & 15;          // V: 16 rows x 64 u32
    cpa16(&Vh[(buf*(BKV/2)+vr)*VSTP + vc*4], Vhg + (size_t)(k0/2+vr)*64 + vc*4);
    if (tid < 8) cpa16(&ms[buf*BKV + tid*4], mrow + k0 + tid*4);
}

__global__ __launch_bounds__(256, 2) void flash_kernel(const int* __restrict__ mask)
{
    extern __shared__ uint32_t smu[];
    uint32_t* Kh = smu;
    uint32_t* Vh = Kh + FK;
    int*      ms = (int*)(smu + FL_MS);
    const uint32_t sbF = (uint32_t)__cvta_generic_to_shared(smu);
    const uint32_t mb1 = sbF + FL_MB*4;
    const uint32_t mb2 = sbF + FL_MB*4 + 32;

    const int tid = threadIdx.x;
    const int lane = tid & 31, w = tid >> 5;
    const int g = lane >> 2, cq = lane & 3;
    const int q0 = blockIdx.x * BQF;
    const int nh = blockIdx.y;
    const int n = nh >> 3, h = nh & 7;
    const uint32_t* Qhg = g_qh + (size_t)nh * SEQ * 32;
    const uint32_t* Qlg = g_ql + (size_t)nh * SEQ * 32;
    const uint32_t* Khg = g_kh + (size_t)nh * SEQ * 32;
    const uint32_t* Vhg = g_vh + (size_t)nh * (SEQ/2) * 64;
    const int* mrow = mask + n * SEQ;
    const int rb = w * 16 + g;

    if (tid == 0) {
        #pragma unroll
        for (int s = 0; s < SFL; s++) {
            MBAR_INIT(mb1 + s*8, 256);
            MBAR_INIT(mb2 + s*8, 256);
        }
    }
    __syncthreads();

    flash_fill(Khg, Vhg, mrow, Kh, Vh, ms, 0, 0, tid);
    CPA_ARRIVE(mb1 + 0*8);
    flash_fill(Khg, Vhg, mrow, Kh, Vh, ms, BKV, 1, tid);
    CPA_ARRIVE(mb1 + 1*8);

    uint32_t qh[4][4], ql[4][4];
    {
        const int r0 = q0 + rb, r1 = r0 + 8;
        #pragma unroll
        for (int ks = 0; ks < 4; ks++) {
            int d0 = ks*8 + cq, d1 = ks*8 + 4 + cq;
            qh[ks][0] = Qhg[(size_t)r0*32 + d0];
            qh[ks][1] = Qhg[(size_t)r1*32 + d0];
            qh[ks][2] = Qhg[(size_t)r0*32 + d1];
            qh[ks][3] = Qhg[(size_t)r1*32 + d1];
            ql[ks][0] = Qlg[(size_t)r0*32 + d0];
            ql[ks][1] = Qlg[(size_t)r1*32 + d0];
            ql[ks][2] = Qlg[(size_t)r0*32 + d1];
            ql[ks][3] = Qlg[(size_t)r1*32 + d1];
        }
    }

    float acc[8][4];
    float mi[2] = {-1e30f, -1e30f}, li[2] = {0.f, 0.f};
    #pragma unroll
    for (int nt = 0; nt < 8; nt++)
        #pragma unroll
        for (int e = 0; e < 4; e++) acc[nt][e] = 0.f;

    for (int t = 0; t < NT; t++) {
        const int f = t + 2;
        if (f < NT) {
            const int s = f & 3;
            if (t >= 2) MBAR_WAIT(mb2 + s*8, ((t - 2) >> 2) & 1);
            flash_fill(Khg, Vhg, mrow, Kh, Vh, ms, f*BKV, s, tid);
            CPA_ARRIVE(mb1 + s*8);
        }

        const int cb = t & 3;
        MBAR_WAIT(mb1 + cb*8, (t >> 2) & 1);

        const uint32_t* KhC = Kh + cb * BKV * KSTP;
        const uint32_t* VhC = Vh + cb * (BKV/2) * VSTP;
        const int*      msC = ms + cb * BKV;

        // ---- S = Q @ K^T (fp16x2: (qh+ql)·kh) ----
        float s[4][4];
        #pragma unroll
        for (int nt = 0; nt < 4; nt++)
            #pragma unroll
            for (int e = 0; e < 4; e++) s[nt][e] = 0.f;

        #pragma unroll
        for (int ks = 0; ks < 4; ks++) {
            int d0 = ks*8 + cq, d1 = ks*8 + 4 + cq;
            uint32_t bh[4][2];
            #pragma unroll
            for (int nt = 0; nt < 4; nt++) {
                int nn = nt*8 + g;
                bh[nt][0] = KhC[nn*KSTP + d0];
                bh[nt][1] = KhC[nn*KSTP + d1];
            }
            #pragma unroll
            for (int nt = 0; nt < 4; nt++) {
                mmah(s[nt], qh[ks], bh[nt]);
                mmah(s[nt], ql[ks], bh[nt]);
            }
        }

        // ---- mask + online softmax (base-2) ----
        float mx0 = -1e30f, mx1 = -1e30f;
        #pragma unroll
        for (int nt = 0; nt < 4; nt++) {
            #pragma unroll
            for (int j = 0; j < 2; j++) {
                int mv = msC[nt*8 + 2*cq + j];
                float v0 = mv ? s[nt][j]   : -1e30f;
                float v1 = mv ? s[nt][2+j] : -1e30f;
                s[nt][j] = v0; s[nt][2+j] = v1;
                mx0 = fmaxf(mx0, v0); mx1 = fmaxf(mx1, v1);
            }
        }
        mx0 = fmaxf(mx0, __shfl_xor_sync(0xffffffffu, mx0, 1));
        mx0 = fmaxf(mx0, __shfl_xor_sync(0xffffffffu, mx0, 2));
        mx1 = fmaxf(mx1, __shfl_xor_sync(0xffffffffu, mx1, 1));
        mx1 = fmaxf(mx1, __shfl_xor_sync(0xffffffffu, mx1, 2));

        float mn0 = fmaxf(mi[0], mx0), mn1 = fmaxf(mi[1], mx1);
        float cr0 = ex2f(mi[0] - mn0), cr1 = ex2f(mi[1] - mn1);
        float sum0 = 0.f, sum1 = 0.f;
        #pragma unroll
        for (int nt = 0; nt < 4; nt++) {
            s[nt][0] = ex2f(s[nt][0] - mn0);
            s[nt][1] = ex2f(s[nt][1] - mn0);
            s[nt][2] = ex2f(s[nt][2] - mn1);
            s[nt][3] = ex2f(s[nt][3] - mn1);
            sum0 += s[nt][0] + s[nt][1];
            sum1 += s[nt][2] + s[nt][3];
        }
        sum0 += __shfl_xor_sync(0xffffffffu, sum0, 1);
        sum0 += __shfl_xor_sync(0xffffffffu, sum0, 2);
        sum1 += __shfl_xor_sync(0xffffffffu, sum1, 1);
        sum1 += __shfl_xor_sync(0xffffffffu, sum1, 2);
        li[0] = li[0] * cr0 + sum0; mi[0] = mn0;
        li[1] = li[1] * cr1 + sum1; mi[1] = mn1;
        #pragma unroll
        for (int nt = 0; nt < 8; nt++) {
            acc[nt][0] *= cr0; acc[nt][1] *= cr0;
            acc[nt][2] *= cr1; acc[nt][3] *= cr1;
        }

        // ---- P fragments: register repack, hi+lo ----
        uint32_t ph[2][4], pl[2][4];
        #pragma unroll
        for (int k2 = 0; k2 < 2; k2++) {
            split_packh(s[2*k2  ][0], s[2*k2  ][1], ph[k2][0], pl[k2][0]);
            split_packh(s[2*k2  ][2], s[2*k2  ][3], ph[k2][1], pl[k2][1]);
            split_packh(s[2*k2+1][0], s[2*k2+1][1], ph[k2][2], pl[k2][2]);
            split_packh(s[2*k2+1][2], s[2*k2+1][3], ph[k2][3], pl[k2][3]);
        }

        // ---- O += P @ V ((ph+pl)·vh) ----
        #pragma unroll
        for (int k2 = 0; k2 < 2; k2++) {
            int sp0 = k2*8 + cq, sp1 = k2*8 + 4 + cq;
            uint32_t vh[8][2];
            #pragma unroll
            for (int nt = 0; nt < 8; nt++) {
                int dd = nt*8 + g;
                vh[nt][0] = VhC[sp0*VSTP + dd];
                vh[nt][1] = VhC[sp1*VSTP + dd];
            }
            #pragma unroll
            for (int nt = 0; nt < 8; nt++) {
                mmah(acc[nt], ph[k2], vh[nt]);
                mmah(acc[nt], pl[k2], vh[nt]);
            }
        }

        MBAR_ARRIVE(mb2 + cb*8);
    }

    // ---- epilogue ----
    float inv0 = 1.f / li[0], inv1 = 1.f / li[1];
    #pragma unroll
    for (int nt = 0; nt < 8; nt++) {
        int col = h * 64 + nt * 8 + 2 * cq;
        size_t r0 = (size_t)(n * SEQ + q0 + rb) * EMB + col;
        size_t r1 = (size_t)(n * SEQ + q0 + rb + 8) * EMB + col;
        *(float2*)&g_ao[r0] = make_float2(acc[nt][0]*inv0, acc[nt][1]*inv0);
        *(float2*)&g_ao[r1] = make_float2(acc[nt][2]*inv1, acc[nt][3]*inv1);
    }
}

// ============================================================
extern "C" void kernel_launch(void* const* d_in, const int* in_sizes, int n_in,
                              void* d_out, int out_size)
{
    const float* values = (const float*)d_in[0];
    const float* keys   = (const float*)d_in[1];
    const float* query  = (const float*)d_in[2];
    const int*   mask   = (const int*)  d_in[3];
    const float* Wv     = (const float*)d_in[4];
    const float* Wk     = (const float*)d_in[5];
    const float* Wq     = (const float*)d_in[6];
    const float* Wo     = (const float*)d_in[7];
    const float* bo     = (const float*)d_in[8];

    split_w<<<dim3(EMB*EMB/2/256, 4), 256>>>(Wv, Wk, Wq, Wo);

    cudaFuncSetAttribute(proj_kernel, cudaFuncAttributeMaxDynamicSharedMemorySize, GEMM_SMEM);
    proj_kernel<<<dim3(EMB/128, NROWS/128, 3), 256, GEMM_SMEM>>>(values, keys, query);

    cudaFuncSetAttribute(flash_kernel, cudaFuncAttributeMaxDynamicSharedMemorySize, FLASH_SMEM);
    flash_kernel<<<dim3(SEQ/BQF, NH), 256, FLASH_SMEM>>>(mask);

    cudaFuncSetAttribute(out_kernel, cudaFuncAttributeMaxDynamicSharedMemorySize, GEMM_SMEM);
    out_kernel<<<dim3(EMB/128, NROWS/128), 256, GEMM_SMEM>>>(bo, (float*)d_out);
}